// round 2
// baseline (speedup 1.0000x reference)
#include <cuda_runtime.h>
#include <cuda_bf16.h>
#include <mma.h>

using namespace nvcuda;

// ---- problem constants ----
#define BD   2
#define CC   256
#define NHH  8
#define NLL  5
#define NPP  16
#define HDD  32
#define MLPH 1024
#define HWW  1024
#define LQQ  5120
#define MM   10240     // B * LQ tokens
#define NPROJ 2176     // 256 + 1280 + 640

// ---- scratch (device globals; no runtime allocation allowed) ----
__device__ __align__(256) __nv_bfloat16 g_q[MM * CC];
__device__ __align__(256) __nv_bfloat16 g_hln[MM * CC];
__device__ __align__(256) __nv_bfloat16 g_samp[MM * CC];
__device__ __align__(256) __nv_bfloat16 g_mh[MM * MLPH];
__device__ __align__(256) __nv_bfloat16 g_vperm[BD * NHH * NLL * HWW * HDD];
__device__ __align__(256) float g_off[MM * 1280];
__device__ __align__(256) float g_aw[MM * 640];
__device__ __align__(256) float g_x1[MM * CC];
__device__ __align__(256) __nv_bfloat16 g_w_proj[CC * NPROJ];
__device__ __align__(256) float g_b_proj[NPROJ];
__device__ __align__(256) __nv_bfloat16 g_w_out[CC * CC];
__device__ __align__(256) __nv_bfloat16 g_w_fc1[CC * MLPH];
__device__ __align__(256) __nv_bfloat16 g_w_fc2[MLPH * CC];

// =====================================================================
// pack weights: fused proj (val|off|attn) + bias, plus out/fc1/fc2 -> bf16
// =====================================================================
#define PACK_PROJ_W (CC * NPROJ)              // 557056
#define PACK_TOTAL  (PACK_PROJ_W + NPROJ + CC*CC + CC*MLPH + MLPH*CC)

__global__ void pack_weights_kernel(const float* __restrict__ wv,
                                    const float* __restrict__ wo,
                                    const float* __restrict__ wa,
                                    const float* __restrict__ bv,
                                    const float* __restrict__ bo,
                                    const float* __restrict__ ba,
                                    const float* __restrict__ wout,
                                    const float* __restrict__ wf1,
                                    const float* __restrict__ wf2) {
    int i = blockIdx.x * 256 + threadIdx.x;
    if (i >= PACK_TOTAL) return;
    if (i < PACK_PROJ_W) {
        int k = i / NPROJ, j = i - k * NPROJ;
        float v;
        if (j < 256)        v = wv[k * 256 + j];
        else if (j < 1536)  v = wo[k * 1280 + (j - 256)];
        else                v = wa[k * 640 + (j - 1536)];
        g_w_proj[i] = __float2bfloat16(v);
        return;
    }
    i -= PACK_PROJ_W;
    if (i < NPROJ) {
        float v;
        if (i < 256)        v = bv[i];
        else if (i < 1536)  v = bo[i - 256];
        else                v = ba[i - 1536];
        g_b_proj[i] = v;
        return;
    }
    i -= NPROJ;
    if (i < CC * CC) { g_w_out[i] = __float2bfloat16(wout[i]); return; }
    i -= CC * CC;
    if (i < CC * MLPH) { g_w_fc1[i] = __float2bfloat16(wf1[i]); return; }
    i -= CC * MLPH;
    g_w_fc2[i] = __float2bfloat16(wf2[i]);
}

// =====================================================================
// LayerNorm over C=256, one warp per row, bf16 output
// =====================================================================
__global__ void ln_kernel(const float* __restrict__ x,
                          const float* __restrict__ gam,
                          const float* __restrict__ bet,
                          __nv_bfloat16* __restrict__ out) {
    int warp = threadIdx.x >> 5, lane = threadIdx.x & 31;
    int row = blockIdx.x * 8 + warp;
    const float4* xp = (const float4*)(x + (size_t)row * CC);
    float4 a = xp[lane * 2];
    float4 b = xp[lane * 2 + 1];
    float s  = a.x + a.y + a.z + a.w + b.x + b.y + b.z + b.w;
    float sq = a.x*a.x + a.y*a.y + a.z*a.z + a.w*a.w
             + b.x*b.x + b.y*b.y + b.z*b.z + b.w*b.w;
#pragma unroll
    for (int o = 16; o > 0; o >>= 1) {
        s  += __shfl_xor_sync(0xffffffffu, s,  o);
        sq += __shfl_xor_sync(0xffffffffu, sq, o);
    }
    float mean = s * (1.0f / CC);
    float var  = sq * (1.0f / CC) - mean * mean;
    float rs   = rsqrtf(var + 1e-5f);
    const float4* gp = (const float4*)gam;
    const float4* bp = (const float4*)bet;
    float4 g0 = gp[lane * 2], g1 = gp[lane * 2 + 1];
    float4 b0 = bp[lane * 2], b1 = bp[lane * 2 + 1];
    float o0 = (a.x - mean) * rs * g0.x + b0.x;
    float o1 = (a.y - mean) * rs * g0.y + b0.y;
    float o2 = (a.z - mean) * rs * g0.z + b0.z;
    float o3 = (a.w - mean) * rs * g0.w + b0.w;
    float o4 = (b.x - mean) * rs * g1.x + b1.x;
    float o5 = (b.y - mean) * rs * g1.y + b1.y;
    float o6 = (b.z - mean) * rs * g1.z + b1.z;
    float o7 = (b.w - mean) * rs * g1.w + b1.w;
    __nv_bfloat162 r0 = __floats2bfloat162_rn(o0, o1);
    __nv_bfloat162 r1 = __floats2bfloat162_rn(o2, o3);
    __nv_bfloat162 r2 = __floats2bfloat162_rn(o4, o5);
    __nv_bfloat162 r3 = __floats2bfloat162_rn(o6, o7);
    uint4 u;
    u.x = *(unsigned int*)&r0; u.y = *(unsigned int*)&r1;
    u.z = *(unsigned int*)&r2; u.w = *(unsigned int*)&r3;
    ((uint4*)(out + (size_t)row * CC))[lane] = u;
}

// =====================================================================
// bf16 GEMM, 128x128 block tile, 8 warps of 64x32, K-step 32,
// 2-stage cp.async double buffering, per-warp staged epilogue.
// projmode=1: fused projection routing (val->vperm bf16, off/attn->f32)
// =====================================================================
#define CP16(dst, src) \
    asm volatile("cp.async.cg.shared.global [%0], [%1], 16;\n" :: "r"(dst), "l"(src))
#define CP_COMMIT() asm volatile("cp.async.commit_group;\n" ::: "memory")
#define CP_WAIT1()  asm volatile("cp.async.wait_group 1;\n" ::: "memory")
#define CP_WAIT0()  asm volatile("cp.async.wait_group 0;\n" ::: "memory")

__global__ __launch_bounds__(256, 2)
void gemm_bf16_kernel(const __nv_bfloat16* __restrict__ A,
                      const __nv_bfloat16* __restrict__ Bw,
                      const float* __restrict__ bias,
                      const float* __restrict__ resid,
                      float* __restrict__ out_f32,
                      __nv_bfloat16* __restrict__ out_bf16,
                      int M, int N, int K, int act, int projmode) {
    __shared__ __align__(16) unsigned char smem[38912];
    // stage s: A at s*10240 (128x40 bf16), B at 20480 + s*8704 (32x136 bf16)
    int bm = blockIdx.y, bn = blockIdx.x;
    int tid = threadIdx.x;
    int w = tid >> 5, lane = tid & 31;
    int wm = w >> 2, wn = w & 3;      // warp grid 2x4 of 64x32 tiles

    wmma::fragment<wmma::accumulator, 16, 16, 16, float> cf[4][2];
#pragma unroll
    for (int i = 0; i < 4; ++i)
#pragma unroll
        for (int j = 0; j < 2; ++j)
            wmma::fill_fragment(cf[i][j], 0.0f);

    const int steps = K >> 5;

    // issue loads for stage `s` k-block `k0`
    auto issue = [&](int buf, int k0) {
        __nv_bfloat16* SA = (__nv_bfloat16*)(smem + buf * 10240);
        __nv_bfloat16* SB = (__nv_bfloat16*)(smem + 20480 + buf * 8704);
#pragma unroll
        for (int u = 0; u < 2; ++u) {
            int c = tid + u * 256;                 // A: 512 chunks of 16B
            int row = c >> 2, col8 = (c & 3) << 3;
            unsigned dst = (unsigned)__cvta_generic_to_shared(SA + row * 40 + col8);
            CP16(dst, A + (size_t)(bm * 128 + row) * K + k0 + col8);
        }
#pragma unroll
        for (int u = 0; u < 2; ++u) {
            int c = tid + u * 256;                 // B: 512 chunks of 16B
            int row = c >> 4, col8 = (c & 15) << 3;
            unsigned dst = (unsigned)__cvta_generic_to_shared(SB + row * 136 + col8);
            CP16(dst, Bw + (size_t)(k0 + row) * N + bn * 128 + col8);
        }
    };

    issue(0, 0);
    CP_COMMIT();

    for (int s = 0; s < steps; ++s) {
        int cur = s & 1;
        if (s + 1 < steps) { issue((s + 1) & 1, (s + 1) << 5); CP_COMMIT(); CP_WAIT1(); }
        else               { CP_WAIT0(); }
        __syncthreads();

        __nv_bfloat16* SA = (__nv_bfloat16*)(smem + cur * 10240);
        __nv_bfloat16* SB = (__nv_bfloat16*)(smem + 20480 + cur * 8704);
#pragma unroll
        for (int kk = 0; kk < 32; kk += 16) {
            wmma::fragment<wmma::matrix_b, 16, 16, 16, __nv_bfloat16, wmma::row_major> bf[2];
#pragma unroll
            for (int j = 0; j < 2; ++j)
                wmma::load_matrix_sync(bf[j], SB + kk * 136 + wn * 32 + j * 16, 136);
#pragma unroll
            for (int i = 0; i < 4; ++i) {
                wmma::fragment<wmma::matrix_a, 16, 16, 16, __nv_bfloat16, wmma::row_major> af;
                wmma::load_matrix_sync(af, SA + (wm * 64 + i * 16) * 40 + kk, 40);
#pragma unroll
                for (int j = 0; j < 2; ++j)
                    wmma::mma_sync(cf[i][j], af, bf[j], cf[i][j]);
            }
        }
        __syncthreads();
    }

    // ---- per-warp staged epilogue: 64x16 f32 chunks ----
    float* stage = (float*)smem + w * 1024;       // 64*16 floats = 4KB per warp
#pragma unroll
    for (int j = 0; j < 2; ++j) {
        __syncwarp();
#pragma unroll
        for (int i = 0; i < 4; ++i)
            wmma::store_matrix_sync(stage + i * 256, cf[i][j], 16, wmma::mem_row_major);
        __syncwarp();
#pragma unroll
        for (int it = 0; it < 32; ++it) {
            int e = it * 32 + lane;
            int r = e >> 4, c = e & 15;
            float v = stage[r * 16 + c];
            int grow = bm * 128 + wm * 64 + r;
            int gcol = bn * 128 + wn * 32 + j * 16 + c;
            if (projmode) {
                v += g_b_proj[gcol];
                if (gcol < 256) {
                    int b = grow / LQQ;
                    int rem = grow - b * LQQ;
                    int l = rem >> 10, yx = rem & 1023;
                    int h = gcol >> 5, d = gcol & 31;
                    g_vperm[((((b * NHH + h) * NLL + l) << 10) + yx) * HDD + d] =
                        __float2bfloat16(v);
                } else if (gcol < 1536) {
                    g_off[(size_t)grow * 1280 + (gcol - 256)] = v;
                } else {
                    g_aw[(size_t)grow * 640 + (gcol - 1536)] = v;
                }
            } else {
                v += bias[gcol];
                if (act) v = 0.5f * v * (1.0f + erff(v * 0.70710678118654752f));
                if (resid) v += resid[(size_t)grow * N + gcol];
                if (out_f32) out_f32[(size_t)grow * N + gcol] = v;
                if (out_bf16) out_bf16[(size_t)grow * N + gcol] = __float2bfloat16(v);
            }
        }
    }
}

// =====================================================================
// softmax over 80 (per token,head), in place on g_aw; one warp per row
// =====================================================================
__global__ void softmax80_kernel() {
    int warp = threadIdx.x >> 5, lane = threadIdx.x & 31;
    int r = blockIdx.x * 8 + warp;                   // 81920 rows
    float* p = g_aw + (size_t)r * 80;
    float v0 = p[lane];
    float v1 = p[lane + 32];
    float v2 = (lane < 16) ? p[lane + 64] : -1e30f;
    float m = fmaxf(fmaxf(v0, v1), v2);
#pragma unroll
    for (int o = 16; o > 0; o >>= 1) m = fmaxf(m, __shfl_xor_sync(0xffffffffu, m, o));
    float e0 = expf(v0 - m), e1 = expf(v1 - m);
    float e2 = (lane < 16) ? expf(v2 - m) : 0.0f;
    float s = e0 + e1 + e2;
#pragma unroll
    for (int o = 16; o > 0; o >>= 1) s += __shfl_xor_sync(0xffffffffu, s, o);
    float inv = 1.0f / s;
    p[lane] = e0 * inv;
    p[lane + 32] = e1 * inv;
    if (lane < 16) p[lane + 64] = e2 * inv;
}

// =====================================================================
// deformable sampling: one warp per (token, head)
// lanes: half = lane>>4 selects x-tap (x0/x1), dp = lane&15 selects d-pair
// =====================================================================
__global__ void sample_kernel(const float* __restrict__ refpts) {
    int warp = threadIdx.x >> 5, lane = threadIdx.x & 31;
    int unit = blockIdx.x * 8 + warp;                // 81920 units
    int token = unit >> 3;
    int h = unit & 7;
    int b = token / LQQ;

    __shared__ float s_off[8][160];
    __shared__ float s_aw[8][80];
    __shared__ float s_ref[8][10];

    const float* offp = g_off + (size_t)token * 1280 + h * 160;
    for (int i = lane; i < 160; i += 32) s_off[warp][i] = offp[i];
    const float* awp = g_aw + (size_t)token * 640 + h * 80;
    for (int i = lane; i < 80; i += 32) s_aw[warp][i] = awp[i];
    const float* rp = refpts + (size_t)token * 10;
    if (lane < 10) s_ref[warp][lane] = rp[lane];
    __syncwarp();

    int half = lane >> 4, dp = lane & 15;
    float accx = 0.0f, accy = 0.0f;

#pragma unroll
    for (int l = 0; l < NLL; ++l) {
        const __nv_bfloat162* vb =
            (const __nv_bfloat162*)g_vperm + ((size_t)((b * NHH + h) * NLL + l) << 14);
        float rx = s_ref[warp][l * 2 + 0] * 32.0f - 0.5f;
        float ry = s_ref[warp][l * 2 + 1] * 32.0f - 0.5f;
#pragma unroll 4
        for (int p = 0; p < NPP; ++p) {
            int s = l * NPP + p;
            float px = rx + s_off[warp][s * 2 + 0];
            float py = ry + s_off[warp][s * 2 + 1];
            float a = s_aw[warp][s];
            float fx0 = floorf(px), fy0 = floorf(py);
            float fx = px - fx0, fy = py - fy0;
            int x0 = (int)fx0, y0 = (int)fy0;
            int xi = x0 + half;
            float wx = half ? fx : (1.0f - fx);
            bool vx = (xi >= 0) && (xi < 32);
            int xc = min(max(xi, 0), 31);
#pragma unroll
            for (int t = 0; t < 2; ++t) {
                int yi = y0 + t;
                float wy = t ? fy : (1.0f - fy);
                bool vy = (yi >= 0) && (yi < 32);
                int yc = min(max(yi, 0), 31);
                float wgt = (vx && vy) ? a * wx * wy : 0.0f;
                __nv_bfloat162 v = vb[((yc << 5) + xc) * 16 + dp];
                float2 vf = __bfloat1622float2(v);
                accx += wgt * vf.x;
                accy += wgt * vf.y;
            }
        }
    }
    accx += __shfl_xor_sync(0xffffffffu, accx, 16);
    accy += __shfl_xor_sync(0xffffffffu, accy, 16);
    if (half == 0) {
        __nv_bfloat162* op = (__nv_bfloat162*)g_samp + (size_t)token * 128 + h * 16 + dp;
        *op = __floats2bfloat162_rn(accx, accy);
    }
}

// =====================================================================
// launch
// =====================================================================
extern "C" void kernel_launch(void* const* d_in, const int* in_sizes, int n_in,
                              void* d_out, int out_size) {
    const float* x      = (const float*)d_in[0];
    const float* refpts = (const float*)d_in[1];
    const float* n3g = (const float*)d_in[4];
    const float* n3b = (const float*)d_in[5];
    const float* n4g = (const float*)d_in[6];
    const float* n4b = (const float*)d_in[7];
    const float* w_off  = (const float*)d_in[8];
    const float* b_off  = (const float*)d_in[9];
    const float* w_attn = (const float*)d_in[10];
    const float* b_attn = (const float*)d_in[11];
    const float* w_val  = (const float*)d_in[12];
    const float* b_val  = (const float*)d_in[13];
    const float* w_out  = (const float*)d_in[14];
    const float* b_out  = (const float*)d_in[15];
    const float* w_fc1  = (const float*)d_in[16];
    const float* b_fc1  = (const float*)d_in[17];
    const float* w_fc2  = (const float*)d_in[18];
    const float* b_fc2  = (const float*)d_in[19];
    float* outp = (float*)d_out;

    void *p_q, *p_hln, *p_samp, *p_mh, *p_x1;
    void *p_wp, *p_wou, *p_wf1, *p_wf2;
    cudaGetSymbolAddress(&p_q, g_q);
    cudaGetSymbolAddress(&p_hln, g_hln);
    cudaGetSymbolAddress(&p_samp, g_samp);
    cudaGetSymbolAddress(&p_mh, g_mh);
    cudaGetSymbolAddress(&p_x1, g_x1);
    cudaGetSymbolAddress(&p_wp, g_w_proj);
    cudaGetSymbolAddress(&p_wou, g_w_out);
    cudaGetSymbolAddress(&p_wf1, g_w_fc1);
    cudaGetSymbolAddress(&p_wf2, g_w_fc2);

    // 1. pack weights (fused proj + others) -> bf16
    pack_weights_kernel<<<(PACK_TOTAL + 255) / 256, 256>>>(
        w_val, w_off, w_attn, b_val, b_off, b_attn, w_out, w_fc1, w_fc2);

    // 2. q = LN(x)  (bf16)
    ln_kernel<<<MM / 8, 256>>>(x, n3g, n3b, (__nv_bfloat16*)p_q);

    // 3. fused projection GEMM (val->vperm, off, attn) N=2176
    gemm_bf16_kernel<<<dim3(NPROJ / 128, MM / 128), 256>>>(
        (const __nv_bfloat16*)p_q, (const __nv_bfloat16*)p_wp, nullptr,
        nullptr, nullptr, nullptr, MM, NPROJ, CC, 0, 1);

    // 4. softmax over 80
    softmax80_kernel<<<MM * NHH / 8, 256>>>();

    // 5. deformable bilinear sampling -> g_samp (bf16)
    sample_kernel<<<MM * NHH / 8, 256>>>(refpts);

    // 6. out-proj + residual(x) -> x1 (f32)
    gemm_bf16_kernel<<<dim3(CC / 128, MM / 128), 256>>>(
        (const __nv_bfloat16*)p_samp, (const __nv_bfloat16*)p_wou, b_out,
        x, (float*)p_x1, nullptr, MM, CC, CC, 0, 0);

    // 7. h = LN(x1) (bf16)
    ln_kernel<<<MM / 8, 256>>>((const float*)p_x1, n4g, n4b, (__nv_bfloat16*)p_hln);

    // 8. fc1 + GELU -> mh (bf16)
    gemm_bf16_kernel<<<dim3(MLPH / 128, MM / 128), 256>>>(
        (const __nv_bfloat16*)p_hln, (const __nv_bfloat16*)p_wf1, b_fc1,
        nullptr, nullptr, (__nv_bfloat16*)p_mh, MM, MLPH, CC, 1, 0);

    // 9. fc2 + residual(x1) -> d_out (f32)
    gemm_bf16_kernel<<<dim3(CC / 128, MM / 128), 256>>>(
        (const __nv_bfloat16*)p_mh, (const __nv_bfloat16*)p_wf2, b_fc2,
        (const float*)p_x1, outp, nullptr, MM, CC, MLPH, 0, 0);
}

// round 3
// speedup vs baseline: 1.6332x; 1.6332x over previous
#include <cuda_runtime.h>
#include <cuda_bf16.h>
#include <mma.h>

using namespace nvcuda;

// ---- problem constants ----
#define BD   2
#define CC   256
#define NHH  8
#define NLL  5
#define NPP  16
#define HDD  32
#define MLPH 1024
#define HWW  1024
#define LQQ  5120
#define MM   10240     // B * LQ tokens
#define NPROJ 2176     // 256 + 1280 + 640

// ---- scratch (device globals; no runtime allocation allowed) ----
__device__ __align__(256) __nv_bfloat16 g_q[MM * CC];
__device__ __align__(256) __nv_bfloat16 g_hln[MM * CC];
__device__ __align__(256) __nv_bfloat16 g_samp[MM * CC];
__device__ __align__(256) __nv_bfloat16 g_mh[MM * MLPH];
__device__ __align__(256) __nv_bfloat16 g_vperm[BD * NHH * NLL * HWW * HDD];
__device__ __align__(256) float g_off[MM * 1280];
__device__ __align__(256) float g_aw[MM * 640];
__device__ __align__(256) float g_x1[MM * CC];
__device__ __align__(256) __nv_bfloat16 g_w_proj[CC * NPROJ];
__device__ __align__(256) float g_b_proj[NPROJ];
__device__ __align__(256) __nv_bfloat16 g_w_out[CC * CC];
__device__ __align__(256) __nv_bfloat16 g_w_fc1[CC * MLPH];
__device__ __align__(256) __nv_bfloat16 g_w_fc2[MLPH * CC];

// =====================================================================
// pack weights (two kernels so the ncu -s 5 slot lands on sample_kernel)
// =====================================================================
#define PACK_PROJ_TOTAL (CC * NPROJ + NPROJ)

__global__ void pack_proj_kernel(const float* __restrict__ wv,
                                 const float* __restrict__ wo,
                                 const float* __restrict__ wa,
                                 const float* __restrict__ bv,
                                 const float* __restrict__ bo,
                                 const float* __restrict__ ba) {
    int i = blockIdx.x * 256 + threadIdx.x;
    if (i >= PACK_PROJ_TOTAL) return;
    if (i < CC * NPROJ) {
        int k = i / NPROJ, j = i - k * NPROJ;
        float v;
        if (j < 256)        v = wv[k * 256 + j];
        else if (j < 1536)  v = wo[k * 1280 + (j - 256)];
        else                v = wa[k * 640 + (j - 1536)];
        g_w_proj[i] = __float2bfloat16(v);
        return;
    }
    i -= CC * NPROJ;
    float v;
    if (i < 256)        v = bv[i];
    else if (i < 1536)  v = bo[i - 256];
    else                v = ba[i - 1536];
    g_b_proj[i] = v;
}

#define PACK_OTHER_TOTAL (CC*CC + CC*MLPH + MLPH*CC)
__global__ void pack_other_kernel(const float* __restrict__ wout,
                                  const float* __restrict__ wf1,
                                  const float* __restrict__ wf2) {
    int i = blockIdx.x * 256 + threadIdx.x;
    if (i < CC * CC) { g_w_out[i] = __float2bfloat16(wout[i]); return; }
    i -= CC * CC;
    if (i < CC * MLPH) { g_w_fc1[i] = __float2bfloat16(wf1[i]); return; }
    i -= CC * MLPH;
    if (i < MLPH * CC) g_w_fc2[i] = __float2bfloat16(wf2[i]);
}

// =====================================================================
// LayerNorm over C=256, one warp per row, bf16 output
// =====================================================================
__global__ void ln_kernel(const float* __restrict__ x,
                          const float* __restrict__ gam,
                          const float* __restrict__ bet,
                          __nv_bfloat16* __restrict__ out) {
    int warp = threadIdx.x >> 5, lane = threadIdx.x & 31;
    int row = blockIdx.x * 8 + warp;
    const float4* xp = (const float4*)(x + (size_t)row * CC);
    float4 a = xp[lane * 2];
    float4 b = xp[lane * 2 + 1];
    float s  = a.x + a.y + a.z + a.w + b.x + b.y + b.z + b.w;
    float sq = a.x*a.x + a.y*a.y + a.z*a.z + a.w*a.w
             + b.x*b.x + b.y*b.y + b.z*b.z + b.w*b.w;
#pragma unroll
    for (int o = 16; o > 0; o >>= 1) {
        s  += __shfl_xor_sync(0xffffffffu, s,  o);
        sq += __shfl_xor_sync(0xffffffffu, sq, o);
    }
    float mean = s * (1.0f / CC);
    float var  = sq * (1.0f / CC) - mean * mean;
    float rs   = rsqrtf(var + 1e-5f);
    const float4* gp = (const float4*)gam;
    const float4* bp = (const float4*)bet;
    float4 g0 = gp[lane * 2], g1 = gp[lane * 2 + 1];
    float4 b0 = bp[lane * 2], b1 = bp[lane * 2 + 1];
    float o0 = (a.x - mean) * rs * g0.x + b0.x;
    float o1 = (a.y - mean) * rs * g0.y + b0.y;
    float o2 = (a.z - mean) * rs * g0.z + b0.z;
    float o3 = (a.w - mean) * rs * g0.w + b0.w;
    float o4 = (b.x - mean) * rs * g1.x + b1.x;
    float o5 = (b.y - mean) * rs * g1.y + b1.y;
    float o6 = (b.z - mean) * rs * g1.z + b1.z;
    float o7 = (b.w - mean) * rs * g1.w + b1.w;
    __nv_bfloat162 r0 = __floats2bfloat162_rn(o0, o1);
    __nv_bfloat162 r1 = __floats2bfloat162_rn(o2, o3);
    __nv_bfloat162 r2 = __floats2bfloat162_rn(o4, o5);
    __nv_bfloat162 r3 = __floats2bfloat162_rn(o6, o7);
    uint4 u;
    u.x = *(unsigned int*)&r0; u.y = *(unsigned int*)&r1;
    u.z = *(unsigned int*)&r2; u.w = *(unsigned int*)&r3;
    ((uint4*)(out + (size_t)row * CC))[lane] = u;
}

// =====================================================================
// bf16 WMMA GEMM (round-1 proven config)
// block 128x64, 8 warps each 32x32, K-step 32
// projmode=1: fused projection epilogue (val->vperm bf16, off/attn->f32)
// =====================================================================
__global__ void gemm_bf16_kernel(const __nv_bfloat16* __restrict__ A,
                                 const __nv_bfloat16* __restrict__ Bw,
                                 const float* __restrict__ bias,
                                 const float* __restrict__ resid,
                                 float* __restrict__ out_f32,
                                 __nv_bfloat16* __restrict__ out_bf16,
                                 int M, int N, int K, int act, int projmode) {
    __shared__ __align__(16) unsigned char smem_raw[34816];
    __nv_bfloat16* sa = (__nv_bfloat16*)smem_raw;                 // 128 x 40
    __nv_bfloat16* sb = (__nv_bfloat16*)(smem_raw + 128 * 40 * 2); // 32 x 72
    float* sc = (float*)smem_raw;                                  // 128 x 68

    int bm = blockIdx.y, bn = blockIdx.x;
    int tid = threadIdx.x;
    int w  = tid >> 5;
    int wm = w >> 1, wn = w & 1;

    wmma::fragment<wmma::accumulator, 16, 16, 16, float> cf[2][2];
#pragma unroll
    for (int i = 0; i < 2; ++i)
#pragma unroll
        for (int j = 0; j < 2; ++j)
            wmma::fill_fragment(cf[i][j], 0.0f);

    for (int k0 = 0; k0 < K; k0 += 32) {
        __syncthreads();
#pragma unroll
        for (int u0 = 0; u0 < 2; ++u0) {
            int u = tid + u0 * 256;
            int row = u >> 2, c8 = (u & 3) << 3;
            *(uint4*)(sa + row * 40 + c8) =
                *(const uint4*)(A + (size_t)(bm * 128 + row) * K + k0 + c8);
        }
        {
            int row = tid >> 3, c8 = (tid & 7) << 3;
            *(uint4*)(sb + row * 72 + c8) =
                *(const uint4*)(Bw + (size_t)(k0 + row) * N + bn * 64 + c8);
        }
        __syncthreads();
#pragma unroll
        for (int kk = 0; kk < 32; kk += 16) {
            wmma::fragment<wmma::matrix_a, 16, 16, 16, __nv_bfloat16, wmma::row_major> af[2];
            wmma::fragment<wmma::matrix_b, 16, 16, 16, __nv_bfloat16, wmma::row_major> bf[2];
#pragma unroll
            for (int i = 0; i < 2; ++i)
                wmma::load_matrix_sync(af[i], sa + (wm * 32 + i * 16) * 40 + kk, 40);
#pragma unroll
            for (int j = 0; j < 2; ++j)
                wmma::load_matrix_sync(bf[j], sb + kk * 72 + wn * 32 + j * 16, 72);
#pragma unroll
            for (int i = 0; i < 2; ++i)
#pragma unroll
                for (int j = 0; j < 2; ++j)
                    wmma::mma_sync(cf[i][j], af[i], bf[j], cf[i][j]);
        }
    }
    __syncthreads();
#pragma unroll
    for (int i = 0; i < 2; ++i)
#pragma unroll
        for (int j = 0; j < 2; ++j)
            wmma::store_matrix_sync(sc + (wm * 32 + i * 16) * 68 + wn * 32 + j * 16,
                                    cf[i][j], 68, wmma::mem_row_major);
    __syncthreads();

    for (int e = tid; e < 128 * 64; e += 256) {
        int row = e >> 6, col = e & 63;
        int grow = bm * 128 + row, gcol = bn * 64 + col;
        float v = sc[row * 68 + col];
        if (projmode) {
            v += g_b_proj[gcol];
            if (gcol < 256) {
                int b = grow / LQQ;
                int rem = grow - b * LQQ;
                int l = rem >> 10, yx = rem & 1023;
                int h = gcol >> 5, d = gcol & 31;
                g_vperm[((((b * NHH + h) * NLL + l) << 10) + yx) * HDD + d] =
                    __float2bfloat16(v);
            } else if (gcol < 1536) {
                g_off[(size_t)grow * 1280 + (gcol - 256)] = v;
            } else {
                g_aw[(size_t)grow * 640 + (gcol - 1536)] = v;
            }
        } else {
            v += bias[gcol];
            if (act) v = 0.5f * v * (1.0f + erff(v * 0.70710678118654752f));
            if (resid) v += resid[(size_t)grow * N + gcol];
            if (out_f32) out_f32[(size_t)grow * N + gcol] = v;
            if (out_bf16) out_bf16[(size_t)grow * N + gcol] = __float2bfloat16(v);
        }
    }
}

// =====================================================================
// softmax over 80 (per token,head), in place on g_aw; one warp per row
// =====================================================================
__global__ void softmax80_kernel() {
    int warp = threadIdx.x >> 5, lane = threadIdx.x & 31;
    int r = blockIdx.x * 8 + warp;                   // 81920 rows
    float* p = g_aw + (size_t)r * 80;
    float v0 = p[lane];
    float v1 = p[lane + 32];
    float v2 = (lane < 16) ? p[lane + 64] : -1e30f;
    float m = fmaxf(fmaxf(v0, v1), v2);
#pragma unroll
    for (int o = 16; o > 0; o >>= 1) m = fmaxf(m, __shfl_xor_sync(0xffffffffu, m, o));
    float e0 = expf(v0 - m), e1 = expf(v1 - m);
    float e2 = (lane < 16) ? expf(v2 - m) : 0.0f;
    float s = e0 + e1 + e2;
#pragma unroll
    for (int o = 16; o > 0; o >>= 1) s += __shfl_xor_sync(0xffffffffu, s, o);
    float inv = 1.0f / s;
    p[lane] = e0 * inv;
    p[lane + 32] = e1 * inv;
    if (lane < 16) p[lane + 64] = e2 * inv;
}

// =====================================================================
// deformable sampling v2: one warp per (token, head)
// lane = sgrp*16 + tap*4 + q :
//   sgrp (bit4)   : which of 2 samples per round
//   tap  (bits2-3): bilinear corner (dx=tap&1, dy=tap>>1)
//   q    (bits0-1): 16B d-slice (d[8q .. 8q+7])
// one LDG.128 per round covers 2 samples x 4 taps x 64B pixel rows.
// per-lane weighted accumulate; single 3-round shfl_xor reduction at end.
// =====================================================================
__global__ void sample_kernel(const float* __restrict__ refpts) {
    int warp = threadIdx.x >> 5, lane = threadIdx.x & 31;
    int unit = blockIdx.x * 8 + warp;                // 81920 units
    int token = unit >> 3;
    int h = unit & 7;
    int b = token / LQQ;

    __shared__ float s_off[8][160];
    __shared__ float s_aw[8][80];
    __shared__ float s_ref[8][10];

    const float* offp = g_off + (size_t)token * 1280 + h * 160;
    for (int i = lane; i < 160; i += 32) s_off[warp][i] = offp[i];
    const float* awp = g_aw + (size_t)token * 640 + h * 80;
    for (int i = lane; i < 80; i += 32) s_aw[warp][i] = awp[i];
    const float* rp = refpts + (size_t)token * 10;
    if (lane < 10) s_ref[warp][lane] = rp[lane];
    __syncwarp();

    int q    = lane & 3;
    int tap  = (lane >> 2) & 3;
    int sgrp = lane >> 4;
    int dx = tap & 1, dy = tap >> 1;

    const __nv_bfloat16* vbase =
        g_vperm + ((size_t)((b * NHH + h) * NLL) << 15);   // level planes of 32768

    float2 acc0 = {0.f, 0.f}, acc1 = {0.f, 0.f}, acc2 = {0.f, 0.f}, acc3 = {0.f, 0.f};

#pragma unroll 5
    for (int r = 0; r < 40; ++r) {
        int s = r * 2 + sgrp;
        int l = s >> 4;
        float px = s_ref[warp][l * 2 + 0] * 32.0f - 0.5f + s_off[warp][s * 2 + 0];
        float py = s_ref[warp][l * 2 + 1] * 32.0f - 0.5f + s_off[warp][s * 2 + 1];
        float a  = s_aw[warp][s];
        float fx0 = floorf(px), fy0 = floorf(py);
        float fx = px - fx0, fy = py - fy0;
        int xi = (int)fx0 + dx;
        int yi = (int)fy0 + dy;
        float wx = dx ? fx : (1.0f - fx);
        float wy = dy ? fy : (1.0f - fy);
        bool ok = (xi >= 0) && (xi < 32) && (yi >= 0) && (yi < 32);
        float wgt = ok ? a * wx * wy : 0.0f;
        int xc = min(max(xi, 0), 31);
        int yc = min(max(yi, 0), 31);
        const uint4* ptr = (const uint4*)(vbase + ((size_t)l << 15) +
                                          (((yc << 5) + xc) << 5)) + q;
        uint4 u = *ptr;
        float2 f0 = __bfloat1622float2(*(__nv_bfloat162*)&u.x);
        float2 f1 = __bfloat1622float2(*(__nv_bfloat162*)&u.y);
        float2 f2 = __bfloat1622float2(*(__nv_bfloat162*)&u.z);
        float2 f3 = __bfloat1622float2(*(__nv_bfloat162*)&u.w);
        acc0.x += wgt * f0.x; acc0.y += wgt * f0.y;
        acc1.x += wgt * f1.x; acc1.y += wgt * f1.y;
        acc2.x += wgt * f2.x; acc2.y += wgt * f2.y;
        acc3.x += wgt * f3.x; acc3.y += wgt * f3.y;
    }

    // reduce over tap (bits 2-3) and sgrp (bit 4)
#pragma unroll
    for (int o = 4; o <= 16; o <<= 1) {
        acc0.x += __shfl_xor_sync(0xffffffffu, acc0.x, o);
        acc0.y += __shfl_xor_sync(0xffffffffu, acc0.y, o);
        acc1.x += __shfl_xor_sync(0xffffffffu, acc1.x, o);
        acc1.y += __shfl_xor_sync(0xffffffffu, acc1.y, o);
        acc2.x += __shfl_xor_sync(0xffffffffu, acc2.x, o);
        acc2.y += __shfl_xor_sync(0xffffffffu, acc2.y, o);
        acc3.x += __shfl_xor_sync(0xffffffffu, acc3.x, o);
        acc3.y += __shfl_xor_sync(0xffffffffu, acc3.y, o);
    }

    if (lane < 4) {
        __nv_bfloat162 r0 = __floats2bfloat162_rn(acc0.x, acc0.y);
        __nv_bfloat162 r1 = __floats2bfloat162_rn(acc1.x, acc1.y);
        __nv_bfloat162 r2 = __floats2bfloat162_rn(acc2.x, acc2.y);
        __nv_bfloat162 r3 = __floats2bfloat162_rn(acc3.x, acc3.y);
        uint4 o;
        o.x = *(unsigned int*)&r0; o.y = *(unsigned int*)&r1;
        o.z = *(unsigned int*)&r2; o.w = *(unsigned int*)&r3;
        ((uint4*)(g_samp + (size_t)token * CC + h * 32))[q] = o;
    }
}

// =====================================================================
// launch
// =====================================================================
extern "C" void kernel_launch(void* const* d_in, const int* in_sizes, int n_in,
                              void* d_out, int out_size) {
    const float* x      = (const float*)d_in[0];
    const float* refpts = (const float*)d_in[1];
    const float* n3g = (const float*)d_in[4];
    const float* n3b = (const float*)d_in[5];
    const float* n4g = (const float*)d_in[6];
    const float* n4b = (const float*)d_in[7];
    const float* w_off  = (const float*)d_in[8];
    const float* b_off  = (const float*)d_in[9];
    const float* w_attn = (const float*)d_in[10];
    const float* b_attn = (const float*)d_in[11];
    const float* w_val  = (const float*)d_in[12];
    const float* b_val  = (const float*)d_in[13];
    const float* w_out  = (const float*)d_in[14];
    const float* b_out  = (const float*)d_in[15];
    const float* w_fc1  = (const float*)d_in[16];
    const float* b_fc1  = (const float*)d_in[17];
    const float* w_fc2  = (const float*)d_in[18];
    const float* b_fc2  = (const float*)d_in[19];
    float* outp = (float*)d_out;

    void *p_q, *p_hln, *p_samp, *p_mh, *p_x1;
    void *p_wp, *p_wou, *p_wf1, *p_wf2;
    cudaGetSymbolAddress(&p_q, g_q);
    cudaGetSymbolAddress(&p_hln, g_hln);
    cudaGetSymbolAddress(&p_samp, g_samp);
    cudaGetSymbolAddress(&p_mh, g_mh);
    cudaGetSymbolAddress(&p_x1, g_x1);
    cudaGetSymbolAddress(&p_wp, g_w_proj);
    cudaGetSymbolAddress(&p_wou, g_w_out);
    cudaGetSymbolAddress(&p_wf1, g_w_fc1);
    cudaGetSymbolAddress(&p_wf2, g_w_fc2);

    // 0-1. pack weights (two launches)
    pack_other_kernel<<<(PACK_OTHER_TOTAL + 255) / 256, 256>>>(w_out, w_fc1, w_fc2);
    pack_proj_kernel<<<(PACK_PROJ_TOTAL + 255) / 256, 256>>>(
        w_val, w_off, w_attn, b_val, b_off, b_attn);

    // 2. q = LN(x)  (bf16)
    ln_kernel<<<MM / 8, 256>>>(x, n3g, n3b, (__nv_bfloat16*)p_q);

    // 3. fused projection GEMM (val->vperm, off, attn) N=2176
    gemm_bf16_kernel<<<dim3(NPROJ / 64, MM / 128), 256>>>(
        (const __nv_bfloat16*)p_q, (const __nv_bfloat16*)p_wp, nullptr,
        nullptr, nullptr, nullptr, MM, NPROJ, CC, 0, 1);

    // 4. softmax over 80
    softmax80_kernel<<<MM * NHH / 8, 256>>>();

    // 5. deformable bilinear sampling -> g_samp (bf16)   [ncu slot]
    sample_kernel<<<MM * NHH / 8, 256>>>(refpts);

    // 6. out-proj + residual(x) -> x1 (f32)
    gemm_bf16_kernel<<<dim3(CC / 64, MM / 128), 256>>>(
        (const __nv_bfloat16*)p_samp, (const __nv_bfloat16*)p_wou, b_out,
        x, (float*)p_x1, nullptr, MM, CC, CC, 0, 0);

    // 7. h = LN(x1) (bf16)
    ln_kernel<<<MM / 8, 256>>>((const float*)p_x1, n4g, n4b, (__nv_bfloat16*)p_hln);

    // 8. fc1 + GELU -> mh (bf16)
    gemm_bf16_kernel<<<dim3(MLPH / 64, MM / 128), 256>>>(
        (const __nv_bfloat16*)p_hln, (const __nv_bfloat16*)p_wf1, b_fc1,
        nullptr, nullptr, (__nv_bfloat16*)p_mh, MM, MLPH, CC, 1, 0);

    // 9. fc2 + residual(x1) -> d_out (f32)
    gemm_bf16_kernel<<<dim3(CC / 64, MM / 128), 256>>>(
        (const __nv_bfloat16*)p_mh, (const __nv_bfloat16*)p_wf2, b_fc2,
        (const float*)p_x1, outp, nullptr, MM, CC, MLPH, 0, 0);
}

// round 5
// speedup vs baseline: 1.6641x; 1.0189x over previous
#include <cuda_runtime.h>
#include <cuda_bf16.h>
#include <mma.h>

using namespace nvcuda;

// ---- problem constants ----
#define BD   2
#define CC   256
#define NHH  8
#define NLL  5
#define NPP  16
#define HDD  32
#define MLPH 1024
#define HWW  1024
#define LQQ  5120
#define MM   10240     // B * LQ tokens
#define NPROJ 2176     // 256 + 1280 + 640

// ---- scratch (device globals; no runtime allocation allowed) ----
__device__ __align__(256) __nv_bfloat16 g_q[MM * CC];
__device__ __align__(256) __nv_bfloat16 g_hln[MM * CC];
__device__ __align__(256) __nv_bfloat16 g_samp[MM * CC];
__device__ __align__(256) __nv_bfloat16 g_mh[MM * MLPH];
__device__ __align__(256) __nv_bfloat16 g_vperm[BD * NHH * NLL * HWW * HDD];
__device__ __align__(256) float g_off[MM * 1280];
__device__ __align__(256) float g_aw[MM * 640];
__device__ __align__(256) float g_x1[MM * CC];
__device__ __align__(256) __nv_bfloat16 g_w_proj[CC * NPROJ];
__device__ __align__(256) float g_b_proj[NPROJ];
__device__ __align__(256) __nv_bfloat16 g_w_out[CC * CC];
__device__ __align__(256) __nv_bfloat16 g_w_fc1[CC * MLPH];
__device__ __align__(256) __nv_bfloat16 g_w_fc2[MLPH * CC];

// =====================================================================
// pack weights: fused proj (val|off|attn) + bias, plus out/fc1/fc2 -> bf16
// (single launch; K-major [K,N] layout as wmma consumes it)
// =====================================================================
#define PACK_PROJ_W (CC * NPROJ)              // 557056
#define PACK_TOTAL  (PACK_PROJ_W + NPROJ + CC*CC + CC*MLPH + MLPH*CC)

__global__ void pack_weights_kernel(const float* __restrict__ wv,
                                    const float* __restrict__ wo,
                                    const float* __restrict__ wa,
                                    const float* __restrict__ bv,
                                    const float* __restrict__ bo,
                                    const float* __restrict__ ba,
                                    const float* __restrict__ wout,
                                    const float* __restrict__ wf1,
                                    const float* __restrict__ wf2) {
    int i = blockIdx.x * 256 + threadIdx.x;
    if (i >= PACK_TOTAL) return;
    if (i < PACK_PROJ_W) {
        int k = i / NPROJ, j = i - k * NPROJ;
        float v;
        if (j < 256)        v = wv[k * 256 + j];
        else if (j < 1536)  v = wo[k * 1280 + (j - 256)];
        else                v = wa[k * 640 + (j - 1536)];
        g_w_proj[i] = __float2bfloat16(v);
        return;
    }
    i -= PACK_PROJ_W;
    if (i < NPROJ) {
        float v;
        if (i < 256)        v = bv[i];
        else if (i < 1536)  v = bo[i - 256];
        else                v = ba[i - 1536];
        g_b_proj[i] = v;
        return;
    }
    i -= NPROJ;
    if (i < CC * CC) { g_w_out[i] = __float2bfloat16(wout[i]); return; }
    i -= CC * CC;
    if (i < CC * MLPH) { g_w_fc1[i] = __float2bfloat16(wf1[i]); return; }
    i -= CC * MLPH;
    g_w_fc2[i] = __float2bfloat16(wf2[i]);
}

// =====================================================================
// LayerNorm over C=256, one warp per row, bf16 output
// =====================================================================
__global__ void ln_kernel(const float* __restrict__ x,
                          const float* __restrict__ gam,
                          const float* __restrict__ bet,
                          __nv_bfloat16* __restrict__ out) {
    int warp = threadIdx.x >> 5, lane = threadIdx.x & 31;
    int row = blockIdx.x * 8 + warp;
    const float4* xp = (const float4*)(x + (size_t)row * CC);
    float4 a = xp[lane * 2];
    float4 b = xp[lane * 2 + 1];
    float s  = a.x + a.y + a.z + a.w + b.x + b.y + b.z + b.w;
    float sq = a.x*a.x + a.y*a.y + a.z*a.z + a.w*a.w
             + b.x*b.x + b.y*b.y + b.z*b.z + b.w*b.w;
#pragma unroll
    for (int o = 16; o > 0; o >>= 1) {
        s  += __shfl_xor_sync(0xffffffffu, s,  o);
        sq += __shfl_xor_sync(0xffffffffu, sq, o);
    }
    float mean = s * (1.0f / CC);
    float var  = sq * (1.0f / CC) - mean * mean;
    float rs   = rsqrtf(var + 1e-5f);
    const float4* gp = (const float4*)gam;
    const float4* bp = (const float4*)bet;
    float4 g0 = gp[lane * 2], g1 = gp[lane * 2 + 1];
    float4 b0 = bp[lane * 2], b1 = bp[lane * 2 + 1];
    float o0 = (a.x - mean) * rs * g0.x + b0.x;
    float o1 = (a.y - mean) * rs * g0.y + b0.y;
    float o2 = (a.z - mean) * rs * g0.z + b0.z;
    float o3 = (a.w - mean) * rs * g0.w + b0.w;
    float o4 = (b.x - mean) * rs * g1.x + b1.x;
    float o5 = (b.y - mean) * rs * g1.y + b1.y;
    float o6 = (b.z - mean) * rs * g1.z + b1.z;
    float o7 = (b.w - mean) * rs * g1.w + b1.w;
    __nv_bfloat162 r0 = __floats2bfloat162_rn(o0, o1);
    __nv_bfloat162 r1 = __floats2bfloat162_rn(o2, o3);
    __nv_bfloat162 r2 = __floats2bfloat162_rn(o4, o5);
    __nv_bfloat162 r3 = __floats2bfloat162_rn(o6, o7);
    uint4 u;
    u.x = *(unsigned int*)&r0; u.y = *(unsigned int*)&r1;
    u.z = *(unsigned int*)&r2; u.w = *(unsigned int*)&r3;
    ((uint4*)(out + (size_t)row * CC))[lane] = u;
}

// =====================================================================
// bf16 WMMA GEMM (round-3 proven config)
// block 128x64, 8 warps each 32x32, K-step 32
// projmode=1: fused projection epilogue (val->vperm bf16, off/attn->f32)
// =====================================================================
__global__ void gemm_bf16_kernel(const __nv_bfloat16* __restrict__ A,
                                 const __nv_bfloat16* __restrict__ Bw,
                                 const float* __restrict__ bias,
                                 const float* __restrict__ resid,
                                 float* __restrict__ out_f32,
                                 __nv_bfloat16* __restrict__ out_bf16,
                                 int M, int N, int K, int act, int projmode) {
    __shared__ __align__(16) unsigned char smem_raw[34816];
    __nv_bfloat16* sa = (__nv_bfloat16*)smem_raw;                 // 128 x 40
    __nv_bfloat16* sb = (__nv_bfloat16*)(smem_raw + 128 * 40 * 2); // 32 x 72
    float* sc = (float*)smem_raw;                                  // 128 x 68

    int bm = blockIdx.y, bn = blockIdx.x;
    int tid = threadIdx.x;
    int w  = tid >> 5;
    int wm = w >> 1, wn = w & 1;

    wmma::fragment<wmma::accumulator, 16, 16, 16, float> cf[2][2];
#pragma unroll
    for (int i = 0; i < 2; ++i)
#pragma unroll
        for (int j = 0; j < 2; ++j)
            wmma::fill_fragment(cf[i][j], 0.0f);

    for (int k0 = 0; k0 < K; k0 += 32) {
        __syncthreads();
#pragma unroll
        for (int u0 = 0; u0 < 2; ++u0) {
            int u = tid + u0 * 256;
            int row = u >> 2, c8 = (u & 3) << 3;
            *(uint4*)(sa + row * 40 + c8) =
                *(const uint4*)(A + (size_t)(bm * 128 + row) * K + k0 + c8);
        }
        {
            int row = tid >> 3, c8 = (tid & 7) << 3;
            *(uint4*)(sb + row * 72 + c8) =
                *(const uint4*)(Bw + (size_t)(k0 + row) * N + bn * 64 + c8);
        }
        __syncthreads();
#pragma unroll
        for (int kk = 0; kk < 32; kk += 16) {
            wmma::fragment<wmma::matrix_a, 16, 16, 16, __nv_bfloat16, wmma::row_major> af[2];
            wmma::fragment<wmma::matrix_b, 16, 16, 16, __nv_bfloat16, wmma::row_major> bf[2];
#pragma unroll
            for (int i = 0; i < 2; ++i)
                wmma::load_matrix_sync(af[i], sa + (wm * 32 + i * 16) * 40 + kk, 40);
#pragma unroll
            for (int j = 0; j < 2; ++j)
                wmma::load_matrix_sync(bf[j], sb + kk * 72 + wn * 32 + j * 16, 72);
#pragma unroll
            for (int i = 0; i < 2; ++i)
#pragma unroll
                for (int j = 0; j < 2; ++j)
                    wmma::mma_sync(cf[i][j], af[i], bf[j], cf[i][j]);
        }
    }
    __syncthreads();
#pragma unroll
    for (int i = 0; i < 2; ++i)
#pragma unroll
        for (int j = 0; j < 2; ++j)
            wmma::store_matrix_sync(sc + (wm * 32 + i * 16) * 68 + wn * 32 + j * 16,
                                    cf[i][j], 68, wmma::mem_row_major);
    __syncthreads();

    for (int e = tid; e < 128 * 64; e += 256) {
        int row = e >> 6, col = e & 63;
        int grow = bm * 128 + row, gcol = bn * 64 + col;
        float v = sc[row * 68 + col];
        if (projmode) {
            v += g_b_proj[gcol];
            if (gcol < 256) {
                int b = grow / LQQ;
                int rem = grow - b * LQQ;
                int l = rem >> 10, yx = rem & 1023;
                int h = gcol >> 5, d = gcol & 31;
                g_vperm[((((b * NHH + h) * NLL + l) << 10) + yx) * HDD + d] =
                    __float2bfloat16(v);
            } else if (gcol < 1536) {
                g_off[(size_t)grow * 1280 + (gcol - 256)] = v;
            } else {
                g_aw[(size_t)grow * 640 + (gcol - 1536)] = v;
            }
        } else {
            v += bias[gcol];
            if (act) v = 0.5f * v * (1.0f + erff(v * 0.70710678118654752f));
            if (resid) v += resid[(size_t)grow * N + gcol];
            if (out_f32) out_f32[(size_t)grow * N + gcol] = v;
            if (out_bf16) out_bf16[(size_t)grow * N + gcol] = __float2bfloat16(v);
        }
    }
}

// =====================================================================
// deformable sampling + fused softmax: one warp per (token, head)
// lane = sgrp*16 + tap*4 + q :
//   sgrp (bit4)   : which of 2 samples per round
//   tap  (bits2-3): bilinear corner (dx=tap&1, dy=tap>>1)
//   q    (bits0-1): 16B d-slice
// =====================================================================
__global__ void sample_kernel(const float* __restrict__ refpts) {
    int warp = threadIdx.x >> 5, lane = threadIdx.x & 31;
    int unit = blockIdx.x * 8 + warp;                // 81920 units
    int token = unit >> 3;
    int h = unit & 7;
    int b = token / LQQ;

    __shared__ float s_off[8][160];
    __shared__ float s_aw[8][80];
    __shared__ float s_ref[8][10];

    const float* offp = g_off + (size_t)token * 1280 + h * 160;
    for (int i = lane; i < 160; i += 32) s_off[warp][i] = offp[i];
    const float* awp = g_aw + (size_t)token * 640 + h * 80;
    for (int i = lane; i < 80; i += 32) s_aw[warp][i] = awp[i];
    const float* rp = refpts + (size_t)token * 10;
    if (lane < 10) s_ref[warp][lane] = rp[lane];
    __syncwarp();

    // ---- softmax over the 80 logits (in smem) ----
    {
        float v0 = s_aw[warp][lane];
        float v1 = s_aw[warp][lane + 32];
        float v2 = (lane < 16) ? s_aw[warp][lane + 64] : -1e30f;
        float m = fmaxf(fmaxf(v0, v1), v2);
#pragma unroll
        for (int o = 16; o > 0; o >>= 1) m = fmaxf(m, __shfl_xor_sync(0xffffffffu, m, o));
        float e0 = expf(v0 - m), e1 = expf(v1 - m);
        float e2 = (lane < 16) ? expf(v2 - m) : 0.0f;
        float s = e0 + e1 + e2;
#pragma unroll
        for (int o = 16; o > 0; o >>= 1) s += __shfl_xor_sync(0xffffffffu, s, o);
        float inv = 1.0f / s;
        s_aw[warp][lane] = e0 * inv;
        s_aw[warp][lane + 32] = e1 * inv;
        if (lane < 16) s_aw[warp][lane + 64] = e2 * inv;
        __syncwarp();
    }

    int q    = lane & 3;
    int tap  = (lane >> 2) & 3;
    int sgrp = lane >> 4;
    int dx = tap & 1, dy = tap >> 1;

    const __nv_bfloat16* vbase =
        g_vperm + ((size_t)((b * NHH + h) * NLL) << 15);   // level planes of 32768

    float2 acc0 = {0.f, 0.f}, acc1 = {0.f, 0.f}, acc2 = {0.f, 0.f}, acc3 = {0.f, 0.f};

#pragma unroll 5
    for (int r = 0; r < 40; ++r) {
        int s = r * 2 + sgrp;
        int l = s >> 4;
        float px = s_ref[warp][l * 2 + 0] * 32.0f - 0.5f + s_off[warp][s * 2 + 0];
        float py = s_ref[warp][l * 2 + 1] * 32.0f - 0.5f + s_off[warp][s * 2 + 1];
        float a  = s_aw[warp][s];
        float fx0 = floorf(px), fy0 = floorf(py);
        float fx = px - fx0, fy = py - fy0;
        int xi = (int)fx0 + dx;
        int yi = (int)fy0 + dy;
        float wx = dx ? fx : (1.0f - fx);
        float wy = dy ? fy : (1.0f - fy);
        bool ok = (xi >= 0) && (xi < 32) && (yi >= 0) && (yi < 32);
        float wgt = ok ? a * wx * wy : 0.0f;
        int xc = min(max(xi, 0), 31);
        int yc = min(max(yi, 0), 31);
        const uint4* ptr = (const uint4*)(vbase + ((size_t)l << 15) +
                                          (((yc << 5) + xc) << 5)) + q;
        uint4 u = *ptr;
        float2 f0 = __bfloat1622float2(*(__nv_bfloat162*)&u.x);
        float2 f1 = __bfloat1622float2(*(__nv_bfloat162*)&u.y);
        float2 f2 = __bfloat1622float2(*(__nv_bfloat162*)&u.z);
        float2 f3 = __bfloat1622float2(*(__nv_bfloat162*)&u.w);
        acc0.x += wgt * f0.x; acc0.y += wgt * f0.y;
        acc1.x += wgt * f1.x; acc1.y += wgt * f1.y;
        acc2.x += wgt * f2.x; acc2.y += wgt * f2.y;
        acc3.x += wgt * f3.x; acc3.y += wgt * f3.y;
    }

    // reduce over tap (bits 2-3) and sgrp (bit 4)
#pragma unroll
    for (int o = 4; o <= 16; o <<= 1) {
        acc0.x += __shfl_xor_sync(0xffffffffu, acc0.x, o);
        acc0.y += __shfl_xor_sync(0xffffffffu, acc0.y, o);
        acc1.x += __shfl_xor_sync(0xffffffffu, acc1.x, o);
        acc1.y += __shfl_xor_sync(0xffffffffu, acc1.y, o);
        acc2.x += __shfl_xor_sync(0xffffffffu, acc2.x, o);
        acc2.y += __shfl_xor_sync(0xffffffffu, acc2.y, o);
        acc3.x += __shfl_xor_sync(0xffffffffu, acc3.x, o);
        acc3.y += __shfl_xor_sync(0xffffffffu, acc3.y, o);
    }

    if (lane < 4) {
        __nv_bfloat162 r0 = __floats2bfloat162_rn(acc0.x, acc0.y);
        __nv_bfloat162 r1 = __floats2bfloat162_rn(acc1.x, acc1.y);
        __nv_bfloat162 r2 = __floats2bfloat162_rn(acc2.x, acc2.y);
        __nv_bfloat162 r3 = __floats2bfloat162_rn(acc3.x, acc3.y);
        uint4 o;
        o.x = *(unsigned int*)&r0; o.y = *(unsigned int*)&r1;
        o.z = *(unsigned int*)&r2; o.w = *(unsigned int*)&r3;
        ((uint4*)(g_samp + (size_t)token * CC + h * 32))[q] = o;
    }
}

// =====================================================================
// launch  (order: pack, ln, gemm_proj, sample <- ncu slot 4)
// =====================================================================
extern "C" void kernel_launch(void* const* d_in, const int* in_sizes, int n_in,
                              void* d_out, int out_size) {
    const float* x      = (const float*)d_in[0];
    const float* refpts = (const float*)d_in[1];
    const float* n3g = (const float*)d_in[4];
    const float* n3b = (const float*)d_in[5];
    const float* n4g = (const float*)d_in[6];
    const float* n4b = (const float*)d_in[7];
    const float* w_off  = (const float*)d_in[8];
    const float* b_off  = (const float*)d_in[9];
    const float* w_attn = (const float*)d_in[10];
    const float* b_attn = (const float*)d_in[11];
    const float* w_val  = (const float*)d_in[12];
    const float* b_val  = (const float*)d_in[13];
    const float* w_out  = (const float*)d_in[14];
    const float* b_out  = (const float*)d_in[15];
    const float* w_fc1  = (const float*)d_in[16];
    const float* b_fc1  = (const float*)d_in[17];
    const float* w_fc2  = (const float*)d_in[18];
    const float* b_fc2  = (const float*)d_in[19];
    float* outp = (float*)d_out;

    void *p_q, *p_hln, *p_samp, *p_mh, *p_x1;
    void *p_wp, *p_wou, *p_wf1, *p_wf2;
    cudaGetSymbolAddress(&p_q, g_q);
    cudaGetSymbolAddress(&p_hln, g_hln);
    cudaGetSymbolAddress(&p_samp, g_samp);
    cudaGetSymbolAddress(&p_mh, g_mh);
    cudaGetSymbolAddress(&p_x1, g_x1);
    cudaGetSymbolAddress(&p_wp, g_w_proj);
    cudaGetSymbolAddress(&p_wou, g_w_out);
    cudaGetSymbolAddress(&p_wf1, g_w_fc1);
    cudaGetSymbolAddress(&p_wf2, g_w_fc2);

    // 1. pack weights (single launch)
    pack_weights_kernel<<<(PACK_TOTAL + 255) / 256, 256>>>(
        w_val, w_off, w_attn, b_val, b_off, b_attn, w_out, w_fc1, w_fc2);

    // 2. q = LN(x)  (bf16)
    ln_kernel<<<MM / 8, 256>>>(x, n3g, n3b, (__nv_bfloat16*)p_q);

    // 3. fused projection GEMM (val->vperm, off, attn) N=2176
    gemm_bf16_kernel<<<dim3(NPROJ / 64, MM / 128), 256>>>(
        (const __nv_bfloat16*)p_q, (const __nv_bfloat16*)p_wp, nullptr,
        nullptr, nullptr, nullptr, MM, NPROJ, CC, 0, 1);

    // 4. deformable bilinear sampling (+fused softmax) -> g_samp  [ncu slot]
    sample_kernel<<<MM * NHH / 8, 256>>>(refpts);

    // 5. out-proj + residual(x) -> x1 (f32)
    gemm_bf16_kernel<<<dim3(CC / 64, MM / 128), 256>>>(
        (const __nv_bfloat16*)p_samp, (const __nv_bfloat16*)p_wou, b_out,
        x, (float*)p_x1, nullptr, MM, CC, CC, 0, 0);

    // 6. h = LN(x1) (bf16)
    ln_kernel<<<MM / 8, 256>>>((const float*)p_x1, n4g, n4b, (__nv_bfloat16*)p_hln);

    // 7. fc1 + GELU -> mh (bf16)
    gemm_bf16_kernel<<<dim3(MLPH / 64, MM / 128), 256>>>(
        (const __nv_bfloat16*)p_hln, (const __nv_bfloat16*)p_wf1, b_fc1,
        nullptr, nullptr, (__nv_bfloat16*)p_mh, MM, MLPH, CC, 1, 0);

    // 8. fc2 + residual(x1) -> d_out (f32)
    gemm_bf16_kernel<<<dim3(CC / 64, MM / 128), 256>>>(
        (const __nv_bfloat16*)p_mh, (const __nv_bfloat16*)p_wf2, b_fc2,
        (const float*)p_x1, outp, nullptr, MM, CC, MLPH, 0, 0);
}

// round 6
// speedup vs baseline: 2.0961x; 1.2596x over previous
#include <cuda_runtime.h>
#include <cuda_bf16.h>
#include <mma.h>

using namespace nvcuda;

// ---- problem constants ----
#define BD   2
#define CC   256
#define NHH  8
#define NLL  5
#define NPP  16
#define HDD  32
#define MLPH 1024
#define HWW  1024
#define LQQ  5120
#define MM   10240     // B * LQ tokens
#define NPROJ 2176     // 256 + 1280 + 640

// ---- scratch (device globals; no runtime allocation allowed) ----
__device__ __align__(256) __nv_bfloat16 g_q[MM * CC];
__device__ __align__(256) __nv_bfloat16 g_hln[MM * CC];
__device__ __align__(256) __nv_bfloat16 g_samp[MM * CC];
__device__ __align__(256) __nv_bfloat16 g_mh[MM * MLPH];
__device__ __align__(256) __nv_bfloat16 g_vperm[BD * NHH * NLL * HWW * HDD];
__device__ __align__(256) float g_off[MM * 1280];
__device__ __align__(256) float g_aw[MM * 640];
__device__ __align__(256) float g_x1[MM * CC];
__device__ __align__(256) __nv_bfloat16 g_w_proj[CC * NPROJ];
__device__ __align__(256) float g_b_proj[NPROJ];
__device__ __align__(256) __nv_bfloat16 g_w_out[CC * CC];
__device__ __align__(256) __nv_bfloat16 g_w_fc1[CC * MLPH];
__device__ __align__(256) __nv_bfloat16 g_w_fc2[MLPH * CC];

// =====================================================================
// pack weights: fused proj (val|off|attn) + bias, plus out/fc1/fc2 -> bf16
// =====================================================================
#define PACK_PROJ_W (CC * NPROJ)              // 557056
#define PACK_TOTAL  (PACK_PROJ_W + NPROJ + CC*CC + CC*MLPH + MLPH*CC)

__global__ void pack_weights_kernel(const float* __restrict__ wv,
                                    const float* __restrict__ wo,
                                    const float* __restrict__ wa,
                                    const float* __restrict__ bv,
                                    const float* __restrict__ bo,
                                    const float* __restrict__ ba,
                                    const float* __restrict__ wout,
                                    const float* __restrict__ wf1,
                                    const float* __restrict__ wf2) {
    int i = blockIdx.x * 256 + threadIdx.x;
    if (i >= PACK_TOTAL) return;
    if (i < PACK_PROJ_W) {
        int k = i / NPROJ, j = i - k * NPROJ;
        float v;
        if (j < 256)        v = wv[k * 256 + j];
        else if (j < 1536)  v = wo[k * 1280 + (j - 256)];
        else                v = wa[k * 640 + (j - 1536)];
        g_w_proj[i] = __float2bfloat16(v);
        return;
    }
    i -= PACK_PROJ_W;
    if (i < NPROJ) {
        float v;
        if (i < 256)        v = bv[i];
        else if (i < 1536)  v = bo[i - 256];
        else                v = ba[i - 1536];
        g_b_proj[i] = v;
        return;
    }
    i -= NPROJ;
    if (i < CC * CC) { g_w_out[i] = __float2bfloat16(wout[i]); return; }
    i -= CC * CC;
    if (i < CC * MLPH) { g_w_fc1[i] = __float2bfloat16(wf1[i]); return; }
    i -= CC * MLPH;
    g_w_fc2[i] = __float2bfloat16(wf2[i]);
}

// =====================================================================
// LayerNorm over C=256, one warp per row, bf16 output
// =====================================================================
__global__ void ln_kernel(const float* __restrict__ x,
                          const float* __restrict__ gam,
                          const float* __restrict__ bet,
                          __nv_bfloat16* __restrict__ out) {
    int warp = threadIdx.x >> 5, lane = threadIdx.x & 31;
    int row = blockIdx.x * 8 + warp;
    const float4* xp = (const float4*)(x + (size_t)row * CC);
    float4 a = xp[lane * 2];
    float4 b = xp[lane * 2 + 1];
    float s  = a.x + a.y + a.z + a.w + b.x + b.y + b.z + b.w;
    float sq = a.x*a.x + a.y*a.y + a.z*a.z + a.w*a.w
             + b.x*b.x + b.y*b.y + b.z*b.z + b.w*b.w;
#pragma unroll
    for (int o = 16; o > 0; o >>= 1) {
        s  += __shfl_xor_sync(0xffffffffu, s,  o);
        sq += __shfl_xor_sync(0xffffffffu, sq, o);
    }
    float mean = s * (1.0f / CC);
    float var  = sq * (1.0f / CC) - mean * mean;
    float rs   = rsqrtf(var + 1e-5f);
    const float4* gp = (const float4*)gam;
    const float4* bp = (const float4*)bet;
    float4 g0 = gp[lane * 2], g1 = gp[lane * 2 + 1];
    float4 b0 = bp[lane * 2], b1 = bp[lane * 2 + 1];
    float o0 = (a.x - mean) * rs * g0.x + b0.x;
    float o1 = (a.y - mean) * rs * g0.y + b0.y;
    float o2 = (a.z - mean) * rs * g0.z + b0.z;
    float o3 = (a.w - mean) * rs * g0.w + b0.w;
    float o4 = (b.x - mean) * rs * g1.x + b1.x;
    float o5 = (b.y - mean) * rs * g1.y + b1.y;
    float o6 = (b.z - mean) * rs * g1.z + b1.z;
    float o7 = (b.w - mean) * rs * g1.w + b1.w;
    __nv_bfloat162 r0 = __floats2bfloat162_rn(o0, o1);
    __nv_bfloat162 r1 = __floats2bfloat162_rn(o2, o3);
    __nv_bfloat162 r2 = __floats2bfloat162_rn(o4, o5);
    __nv_bfloat162 r3 = __floats2bfloat162_rn(o6, o7);
    uint4 u;
    u.x = *(unsigned int*)&r0; u.y = *(unsigned int*)&r1;
    u.z = *(unsigned int*)&r2; u.w = *(unsigned int*)&r3;
    ((uint4*)(out + (size_t)row * CC))[lane] = u;
}

// =====================================================================
// bf16 WMMA GEMM (proven config)
// block 128x64, 8 warps each 32x32, K-step 32
// projmode=1: fused projection epilogue (val->vperm bf16, off/attn->f32)
// =====================================================================
__global__ void gemm_bf16_kernel(const __nv_bfloat16* __restrict__ A,
                                 const __nv_bfloat16* __restrict__ Bw,
                                 const float* __restrict__ bias,
                                 const float* __restrict__ resid,
                                 float* __restrict__ out_f32,
                                 __nv_bfloat16* __restrict__ out_bf16,
                                 int M, int N, int K, int act, int projmode) {
    __shared__ __align__(16) unsigned char smem_raw[34816];
    __nv_bfloat16* sa = (__nv_bfloat16*)smem_raw;                 // 128 x 40
    __nv_bfloat16* sb = (__nv_bfloat16*)(smem_raw + 128 * 40 * 2); // 32 x 72
    float* sc = (float*)smem_raw;                                  // 128 x 68

    int bm = blockIdx.y, bn = blockIdx.x;
    int tid = threadIdx.x;
    int w  = tid >> 5;
    int wm = w >> 1, wn = w & 1;

    wmma::fragment<wmma::accumulator, 16, 16, 16, float> cf[2][2];
#pragma unroll
    for (int i = 0; i < 2; ++i)
#pragma unroll
        for (int j = 0; j < 2; ++j)
            wmma::fill_fragment(cf[i][j], 0.0f);

    for (int k0 = 0; k0 < K; k0 += 32) {
        __syncthreads();
#pragma unroll
        for (int u0 = 0; u0 < 2; ++u0) {
            int u = tid + u0 * 256;
            int row = u >> 2, c8 = (u & 3) << 3;
            *(uint4*)(sa + row * 40 + c8) =
                *(const uint4*)(A + (size_t)(bm * 128 + row) * K + k0 + c8);
        }
        {
            int row = tid >> 3, c8 = (tid & 7) << 3;
            *(uint4*)(sb + row * 72 + c8) =
                *(const uint4*)(Bw + (size_t)(k0 + row) * N + bn * 64 + c8);
        }
        __syncthreads();
#pragma unroll
        for (int kk = 0; kk < 32; kk += 16) {
            wmma::fragment<wmma::matrix_a, 16, 16, 16, __nv_bfloat16, wmma::row_major> af[2];
            wmma::fragment<wmma::matrix_b, 16, 16, 16, __nv_bfloat16, wmma::row_major> bf[2];
#pragma unroll
            for (int i = 0; i < 2; ++i)
                wmma::load_matrix_sync(af[i], sa + (wm * 32 + i * 16) * 40 + kk, 40);
#pragma unroll
            for (int j = 0; j < 2; ++j)
                wmma::load_matrix_sync(bf[j], sb + kk * 72 + wn * 32 + j * 16, 72);
#pragma unroll
            for (int i = 0; i < 2; ++i)
#pragma unroll
                for (int j = 0; j < 2; ++j)
                    wmma::mma_sync(cf[i][j], af[i], bf[j], cf[i][j]);
        }
    }
    __syncthreads();
#pragma unroll
    for (int i = 0; i < 2; ++i)
#pragma unroll
        for (int j = 0; j < 2; ++j)
            wmma::store_matrix_sync(sc + (wm * 32 + i * 16) * 68 + wn * 32 + j * 16,
                                    cf[i][j], 68, wmma::mem_row_major);
    __syncthreads();

    for (int e = tid; e < 128 * 64; e += 256) {
        int row = e >> 6, col = e & 63;
        int grow = bm * 128 + row, gcol = bn * 64 + col;
        float v = sc[row * 68 + col];
        if (projmode) {
            v += g_b_proj[gcol];
            if (gcol < 256) {
                int b = grow / LQQ;
                int rem = grow - b * LQQ;
                int l = rem >> 10, yx = rem & 1023;
                int h = gcol >> 5, d = gcol & 31;
                g_vperm[((((b * NHH + h) * NLL + l) << 10) + yx) * HDD + d] =
                    __float2bfloat16(v);
            } else if (gcol < 1536) {
                g_off[(size_t)grow * 1280 + (gcol - 256)] = v;
            } else {
                g_aw[(size_t)grow * 640 + (gcol - 1536)] = v;
            }
        } else {
            v += bias[gcol];
            if (act) v = 0.5f * v * (1.0f + erff(v * 0.70710678118654752f));
            if (resid) v += resid[(size_t)grow * N + gcol];
            if (out_f32) out_f32[(size_t)grow * N + gcol] = v;
            if (out_bf16) out_bf16[(size_t)grow * N + gcol] = __float2bfloat16(v);
        }
    }
}

// =====================================================================
// deformable sampling v3: two-phase, one warp per (token, head)
// Phase 1: lanes own samples; softmax + tap weights/offsets -> smem
// Phase 2: lane = sgrp*16 + tap*4 + q; LDS.64 (wgt,off) + LDG.128 + FMA
// =====================================================================
__global__ void sample_kernel(const float* __restrict__ refpts) {
    int warp = threadIdx.x >> 5, lane = threadIdx.x & 31;
    int unit = blockIdx.x * 8 + warp;                // 81920 units
    int token = unit >> 3;
    int h = unit & 7;
    int b = token / LQQ;

    __shared__ float s_aw[8][80];
    __shared__ float s_ref[8][10];
    __shared__ __align__(16) float s_wo[8][80 * 8];  // per sample: 4 x (wgt, off)

    // load attention logits + reference points
    const float* awp = g_aw + (size_t)token * 640 + h * 80;
    for (int i = lane; i < 80; i += 32) s_aw[warp][i] = awp[i];
    const float* rp = refpts + (size_t)token * 10;
    if (lane < 10) s_ref[warp][lane] = rp[lane];
    __syncwarp();

    // ---- softmax over the 80 logits ----
    {
        float v0 = s_aw[warp][lane];
        float v1 = s_aw[warp][lane + 32];
        float v2 = (lane < 16) ? s_aw[warp][lane + 64] : -1e30f;
        float m = fmaxf(fmaxf(v0, v1), v2);
#pragma unroll
        for (int o = 16; o > 0; o >>= 1) m = fmaxf(m, __shfl_xor_sync(0xffffffffu, m, o));
        float e0 = expf(v0 - m), e1 = expf(v1 - m);
        float e2 = (lane < 16) ? expf(v2 - m) : 0.0f;
        float s = e0 + e1 + e2;
#pragma unroll
        for (int o = 16; o > 0; o >>= 1) s += __shfl_xor_sync(0xffffffffu, s, o);
        float inv = 1.0f / s;
        s_aw[warp][lane] = e0 * inv;
        s_aw[warp][lane + 32] = e1 * inv;
        if (lane < 16) s_aw[warp][lane + 64] = e2 * inv;
        __syncwarp();
    }

    // ---- phase 1: per-sample tap weights + element offsets ----
    const float2* offp = (const float2*)(g_off + (size_t)token * 1280 + h * 160);
#pragma unroll
    for (int si = lane; si < 80; si += 32) {
        int l = si >> 4;
        float2 of = offp[si];
        float px = s_ref[warp][l * 2 + 0] * 32.0f - 0.5f + of.x;
        float py = s_ref[warp][l * 2 + 1] * 32.0f - 0.5f + of.y;
        float a  = s_aw[warp][si];
        float fx0 = floorf(px), fy0 = floorf(py);
        float fx = px - fx0, fy = py - fy0;
        int x0 = (int)fx0, y0 = (int)fy0;
        int lbase = l << 15;
        float4 pk0, pk1;
        {   // tap 0: (dx=0,dy=0)
            bool ok = (x0 >= 0) && (x0 < 32) && (y0 >= 0) && (y0 < 32);
            int xc = min(max(x0, 0), 31), yc = min(max(y0, 0), 31);
            pk0.x = ok ? a * (1.0f - fx) * (1.0f - fy) : 0.0f;
            pk0.y = __int_as_float(lbase + (((yc << 5) + xc) << 5));
        }
        {   // tap 1: (dx=1,dy=0)
            int xi = x0 + 1;
            bool ok = (xi >= 0) && (xi < 32) && (y0 >= 0) && (y0 < 32);
            int xc = min(max(xi, 0), 31), yc = min(max(y0, 0), 31);
            pk0.z = ok ? a * fx * (1.0f - fy) : 0.0f;
            pk0.w = __int_as_float(lbase + (((yc << 5) + xc) << 5));
        }
        {   // tap 2: (dx=0,dy=1)
            int yi = y0 + 1;
            bool ok = (x0 >= 0) && (x0 < 32) && (yi >= 0) && (yi < 32);
            int xc = min(max(x0, 0), 31), yc = min(max(yi, 0), 31);
            pk1.x = ok ? a * (1.0f - fx) * fy : 0.0f;
            pk1.y = __int_as_float(lbase + (((yc << 5) + xc) << 5));
        }
        {   // tap 3: (dx=1,dy=1)
            int xi = x0 + 1, yi = y0 + 1;
            bool ok = (xi >= 0) && (xi < 32) && (yi >= 0) && (yi < 32);
            int xc = min(max(xi, 0), 31), yc = min(max(yi, 0), 31);
            pk1.z = ok ? a * fx * fy : 0.0f;
            pk1.w = __int_as_float(lbase + (((yc << 5) + xc) << 5));
        }
        *(float4*)&s_wo[warp][si * 8]     = pk0;
        *(float4*)&s_wo[warp][si * 8 + 4] = pk1;
    }
    __syncwarp();

    // ---- phase 2: load + accumulate ----
    int q    = lane & 3;
    int tap  = (lane >> 2) & 3;
    int sgrp = lane >> 4;
    const float* wo = &s_wo[warp][tap * 2];
    const __nv_bfloat16* vbase =
        g_vperm + ((size_t)((b * NHH + h) * NLL) << 15) + (q << 3);

    float2 acc0 = {0.f, 0.f}, acc1 = {0.f, 0.f}, acc2 = {0.f, 0.f}, acc3 = {0.f, 0.f};

#pragma unroll 8
    for (int r = 0; r < 40; ++r) {
        int s = r * 2 + sgrp;
        float2 p = *(const float2*)(wo + s * 8);
        float wgt = p.x;
        int off_el = __float_as_int(p.y);
        uint4 u = *(const uint4*)(vbase + off_el);
        float2 f0 = __bfloat1622float2(*(__nv_bfloat162*)&u.x);
        float2 f1 = __bfloat1622float2(*(__nv_bfloat162*)&u.y);
        float2 f2 = __bfloat1622float2(*(__nv_bfloat162*)&u.z);
        float2 f3 = __bfloat1622float2(*(__nv_bfloat162*)&u.w);
        acc0.x += wgt * f0.x; acc0.y += wgt * f0.y;
        acc1.x += wgt * f1.x; acc1.y += wgt * f1.y;
        acc2.x += wgt * f2.x; acc2.y += wgt * f2.y;
        acc3.x += wgt * f3.x; acc3.y += wgt * f3.y;
    }

    // reduce over tap (bits 2-3) and sgrp (bit 4)
#pragma unroll
    for (int o = 4; o <= 16; o <<= 1) {
        acc0.x += __shfl_xor_sync(0xffffffffu, acc0.x, o);
        acc0.y += __shfl_xor_sync(0xffffffffu, acc0.y, o);
        acc1.x += __shfl_xor_sync(0xffffffffu, acc1.x, o);
        acc1.y += __shfl_xor_sync(0xffffffffu, acc1.y, o);
        acc2.x += __shfl_xor_sync(0xffffffffu, acc2.x, o);
        acc2.y += __shfl_xor_sync(0xffffffffu, acc2.y, o);
        acc3.x += __shfl_xor_sync(0xffffffffu, acc3.x, o);
        acc3.y += __shfl_xor_sync(0xffffffffu, acc3.y, o);
    }

    if (lane < 4) {
        __nv_bfloat162 r0 = __floats2bfloat162_rn(acc0.x, acc0.y);
        __nv_bfloat162 r1 = __floats2bfloat162_rn(acc1.x, acc1.y);
        __nv_bfloat162 r2 = __floats2bfloat162_rn(acc2.x, acc2.y);
        __nv_bfloat162 r3 = __floats2bfloat162_rn(acc3.x, acc3.y);
        uint4 o;
        o.x = *(unsigned int*)&r0; o.y = *(unsigned int*)&r1;
        o.z = *(unsigned int*)&r2; o.w = *(unsigned int*)&r3;
        ((uint4*)(g_samp + (size_t)token * CC + h * 32))[q] = o;
    }
}

// =====================================================================
// launch  (order: pack, ln, gemm_proj, sample <- ncu slot 4)
// =====================================================================
extern "C" void kernel_launch(void* const* d_in, const int* in_sizes, int n_in,
                              void* d_out, int out_size) {
    const float* x      = (const float*)d_in[0];
    const float* refpts = (const float*)d_in[1];
    const float* n3g = (const float*)d_in[4];
    const float* n3b = (const float*)d_in[5];
    const float* n4g = (const float*)d_in[6];
    const float* n4b = (const float*)d_in[7];
    const float* w_off  = (const float*)d_in[8];
    const float* b_off  = (const float*)d_in[9];
    const float* w_attn = (const float*)d_in[10];
    const float* b_attn = (const float*)d_in[11];
    const float* w_val  = (const float*)d_in[12];
    const float* b_val  = (const float*)d_in[13];
    const float* w_out  = (const float*)d_in[14];
    const float* b_out  = (const float*)d_in[15];
    const float* w_fc1  = (const float*)d_in[16];
    const float* b_fc1  = (const float*)d_in[17];
    const float* w_fc2  = (const float*)d_in[18];
    const float* b_fc2  = (const float*)d_in[19];
    float* outp = (float*)d_out;

    void *p_q, *p_hln, *p_samp, *p_mh, *p_x1;
    void *p_wp, *p_wou, *p_wf1, *p_wf2;
    cudaGetSymbolAddress(&p_q, g_q);
    cudaGetSymbolAddress(&p_hln, g_hln);
    cudaGetSymbolAddress(&p_samp, g_samp);
    cudaGetSymbolAddress(&p_mh, g_mh);
    cudaGetSymbolAddress(&p_x1, g_x1);
    cudaGetSymbolAddress(&p_wp, g_w_proj);
    cudaGetSymbolAddress(&p_wou, g_w_out);
    cudaGetSymbolAddress(&p_wf1, g_w_fc1);
    cudaGetSymbolAddress(&p_wf2, g_w_fc2);

    // 1. pack weights (single launch)
    pack_weights_kernel<<<(PACK_TOTAL + 255) / 256, 256>>>(
        w_val, w_off, w_attn, b_val, b_off, b_attn, w_out, w_fc1, w_fc2);

    // 2. q = LN(x)  (bf16)
    ln_kernel<<<MM / 8, 256>>>(x, n3g, n3b, (__nv_bfloat16*)p_q);

    // 3. fused projection GEMM (val->vperm, off, attn) N=2176
    gemm_bf16_kernel<<<dim3(NPROJ / 64, MM / 128), 256>>>(
        (const __nv_bfloat16*)p_q, (const __nv_bfloat16*)p_wp, nullptr,
        nullptr, nullptr, nullptr, MM, NPROJ, CC, 0, 1);

    // 4. deformable sampling v3 (+fused softmax) -> g_samp  [ncu slot]
    sample_kernel<<<MM * NHH / 8, 256>>>(refpts);

    // 5. out-proj + residual(x) -> x1 (f32)
    gemm_bf16_kernel<<<dim3(CC / 64, MM / 128), 256>>>(
        (const __nv_bfloat16*)p_samp, (const __nv_bfloat16*)p_wou, b_out,
        x, (float*)p_x1, nullptr, MM, CC, CC, 0, 0);

    // 6. h = LN(x1) (bf16)
    ln_kernel<<<MM / 8, 256>>>((const float*)p_x1, n4g, n4b, (__nv_bfloat16*)p_hln);

    // 7. fc1 + GELU -> mh (bf16)
    gemm_bf16_kernel<<<dim3(MLPH / 64, MM / 128), 256>>>(
        (const __nv_bfloat16*)p_hln, (const __nv_bfloat16*)p_wf1, b_fc1,
        nullptr, nullptr, (__nv_bfloat16*)p_mh, MM, MLPH, CC, 1, 0);

    // 8. fc2 + residual(x1) -> d_out (f32)
    gemm_bf16_kernel<<<dim3(CC / 64, MM / 128), 256>>>(
        (const __nv_bfloat16*)p_mh, (const __nv_bfloat16*)p_wf2, b_fc2,
        (const float*)p_x1, outp, nullptr, MM, CC, MLPH, 0, 0);
}

// round 8
// speedup vs baseline: 2.2034x; 1.0512x over previous
#include <cuda_runtime.h>
#include <cuda_bf16.h>
#include <mma.h>
#include <cstdint>

using namespace nvcuda;

// ---- problem constants ----
#define BD   2
#define CC   256
#define NHH  8
#define NLL  5
#define NPP  16
#define HDD  32
#define MLPH 1024
#define HWW  1024
#define LQQ  5120
#define MM   10240     // B * LQ tokens
#define NPROJ 2176     // 256 + 1280 + 640

// ---- scratch (device globals; no runtime allocation allowed) ----
__device__ __align__(256) __nv_bfloat16 g_q[MM * CC];
__device__ __align__(256) __nv_bfloat16 g_hln[MM * CC];
__device__ __align__(256) __nv_bfloat16 g_samp[MM * CC];
__device__ __align__(256) __nv_bfloat16 g_mh[MM * MLPH];
__device__ __align__(256) __nv_bfloat16 g_vperm[BD * NHH * NLL * HWW * HDD];
__device__ __align__(256) float g_off[MM * 1280];
__device__ __align__(256) float g_aw[MM * 640];
__device__ __align__(256) float g_x1[MM * CC];
__device__ __align__(256) __nv_bfloat16 g_w_proj[CC * NPROJ];
__device__ __align__(256) float g_b_proj[NPROJ];
__device__ __align__(256) __nv_bfloat16 g_w_out[CC * CC];
__device__ __align__(256) __nv_bfloat16 g_w_fc1[CC * MLPH];
__device__ __align__(256) __nv_bfloat16 g_w_fc2[MLPH * CC];

// =====================================================================
// pack weights (two kernels so ncu slot 4 = proj GEMM)
// =====================================================================
#define PACK_PROJ_TOTAL (CC * NPROJ + NPROJ)

__global__ void pack_proj_kernel(const float* __restrict__ wv,
                                 const float* __restrict__ wo,
                                 const float* __restrict__ wa,
                                 const float* __restrict__ bv,
                                 const float* __restrict__ bo,
                                 const float* __restrict__ ba) {
    int i = blockIdx.x * 256 + threadIdx.x;
    if (i >= PACK_PROJ_TOTAL) return;
    if (i < CC * NPROJ) {
        int k = i / NPROJ, j = i - k * NPROJ;
        float v;
        if (j < 256)        v = wv[k * 256 + j];
        else if (j < 1536)  v = wo[k * 1280 + (j - 256)];
        else                v = wa[k * 640 + (j - 1536)];
        g_w_proj[i] = __float2bfloat16(v);
        return;
    }
    i -= CC * NPROJ;
    float v;
    if (i < 256)        v = bv[i];
    else if (i < 1536)  v = bo[i - 256];
    else                v = ba[i - 1536];
    g_b_proj[i] = v;
}

#define PACK_OTHER_TOTAL (CC*CC + CC*MLPH + MLPH*CC)
__global__ void pack_other_kernel(const float* __restrict__ wout,
                                  const float* __restrict__ wf1,
                                  const float* __restrict__ wf2) {
    int i = blockIdx.x * 256 + threadIdx.x;
    if (i < CC * CC) { g_w_out[i] = __float2bfloat16(wout[i]); return; }
    i -= CC * CC;
    if (i < CC * MLPH) { g_w_fc1[i] = __float2bfloat16(wf1[i]); return; }
    i -= CC * MLPH;
    if (i < MLPH * CC) g_w_fc2[i] = __float2bfloat16(wf2[i]);
}

// =====================================================================
// LayerNorm over C=256, one warp per row, bf16 output
// =====================================================================
__global__ void ln_kernel(const float* __restrict__ x,
                          const float* __restrict__ gam,
                          const float* __restrict__ bet,
                          __nv_bfloat16* __restrict__ out) {
    int warp = threadIdx.x >> 5, lane = threadIdx.x & 31;
    int row = blockIdx.x * 8 + warp;
    const float4* xp = (const float4*)(x + (size_t)row * CC);
    float4 a = xp[lane * 2];
    float4 b = xp[lane * 2 + 1];
    float s  = a.x + a.y + a.z + a.w + b.x + b.y + b.z + b.w;
    float sq = a.x*a.x + a.y*a.y + a.z*a.z + a.w*a.w
             + b.x*b.x + b.y*b.y + b.z*b.z + b.w*b.w;
#pragma unroll
    for (int o = 16; o > 0; o >>= 1) {
        s  += __shfl_xor_sync(0xffffffffu, s,  o);
        sq += __shfl_xor_sync(0xffffffffu, sq, o);
    }
    float mean = s * (1.0f / CC);
    float var  = sq * (1.0f / CC) - mean * mean;
    float rs   = rsqrtf(var + 1e-5f);
    const float4* gp = (const float4*)gam;
    const float4* bp = (const float4*)bet;
    float4 g0 = gp[lane * 2], g1 = gp[lane * 2 + 1];
    float4 b0 = bp[lane * 2], b1 = bp[lane * 2 + 1];
    float o0 = (a.x - mean) * rs * g0.x + b0.x;
    float o1 = (a.y - mean) * rs * g0.y + b0.y;
    float o2 = (a.z - mean) * rs * g0.z + b0.z;
    float o3 = (a.w - mean) * rs * g0.w + b0.w;
    float o4 = (b.x - mean) * rs * g1.x + b1.x;
    float o5 = (b.y - mean) * rs * g1.y + b1.y;
    float o6 = (b.z - mean) * rs * g1.z + b1.z;
    float o7 = (b.w - mean) * rs * g1.w + b1.w;
    __nv_bfloat162 r0 = __floats2bfloat162_rn(o0, o1);
    __nv_bfloat162 r1 = __floats2bfloat162_rn(o2, o3);
    __nv_bfloat162 r2 = __floats2bfloat162_rn(o4, o5);
    __nv_bfloat162 r3 = __floats2bfloat162_rn(o6, o7);
    uint4 u;
    u.x = *(unsigned int*)&r0; u.y = *(unsigned int*)&r1;
    u.z = *(unsigned int*)&r2; u.w = *(unsigned int*)&r3;
    ((uint4*)(out + (size_t)row * CC))[lane] = u;
}

// =====================================================================
// bf16 WMMA GEMM v2b: block 128x128, 8 warps (4x2) of 32x64, K-step 32.
// Per kk: 6 fragment loads : 8 MMAs. Per-warp staged epilogue,
// stage stride 36 floats (144B, 16B-multiple as wmma requires).
// projmode=1: fused projection epilogue (val->vperm bf16, off/attn->f32)
// =====================================================================
__global__ void gemm_bf16_kernel(const __nv_bfloat16* __restrict__ A,
                                 const __nv_bfloat16* __restrict__ Bw,
                                 const float* __restrict__ bias,
                                 const float* __restrict__ resid,
                                 float* __restrict__ out_f32,
                                 __nv_bfloat16* __restrict__ out_bf16,
                                 int M, int N, int K, int act, int projmode) {
    __shared__ __align__(16) unsigned char smem_raw[36864];
    __nv_bfloat16* sa = (__nv_bfloat16*)smem_raw;                  // 128 x 40
    __nv_bfloat16* sb = (__nv_bfloat16*)(smem_raw + 10240);        // 32 x 136

    int bm = blockIdx.y, bn = blockIdx.x;
    int tid = threadIdx.x;
    int w  = tid >> 5, lane = tid & 31;
    int wm = w >> 1, wn = w & 1;          // 4x2 warps, each 32(M) x 64(N)

    wmma::fragment<wmma::accumulator, 16, 16, 16, float> cf[2][4];
#pragma unroll
    for (int i = 0; i < 2; ++i)
#pragma unroll
        for (int j = 0; j < 4; ++j)
            wmma::fill_fragment(cf[i][j], 0.0f);

    for (int k0 = 0; k0 < K; k0 += 32) {
        __syncthreads();
#pragma unroll
        for (int u0 = 0; u0 < 2; ++u0) {        // A: 512 x 16B
            int c = tid + u0 * 256;
            int row = c >> 2, c8 = (c & 3) << 3;
            *(uint4*)(sa + row * 40 + c8) =
                *(const uint4*)(A + (size_t)(bm * 128 + row) * K + k0 + c8);
        }
#pragma unroll
        for (int u0 = 0; u0 < 2; ++u0) {        // B: 512 x 16B
            int c = tid + u0 * 256;
            int row = c >> 4, c8 = (c & 15) << 3;
            *(uint4*)(sb + row * 136 + c8) =
                *(const uint4*)(Bw + (size_t)(k0 + row) * N + bn * 128 + c8);
        }
        __syncthreads();
#pragma unroll
        for (int kk = 0; kk < 32; kk += 16) {
            wmma::fragment<wmma::matrix_a, 16, 16, 16, __nv_bfloat16, wmma::row_major> af[2];
            wmma::fragment<wmma::matrix_b, 16, 16, 16, __nv_bfloat16, wmma::row_major> bf[4];
#pragma unroll
            for (int i = 0; i < 2; ++i)
                wmma::load_matrix_sync(af[i], sa + (wm * 32 + i * 16) * 40 + kk, 40);
#pragma unroll
            for (int j = 0; j < 4; ++j)
                wmma::load_matrix_sync(bf[j], sb + kk * 136 + wn * 64 + j * 16, 136);
#pragma unroll
            for (int i = 0; i < 2; ++i)
#pragma unroll
                for (int j = 0; j < 4; ++j)
                    wmma::mma_sync(cf[i][j], af[i], bf[j], cf[i][j]);
        }
    }
    __syncthreads();

    // per-warp staged epilogue: two 32x32 passes, stage stride 36 (16B mult)
    float* stage = (float*)smem_raw + w * 1152;   // 32*36 floats = 4608B/warp
#pragma unroll
    for (int jh = 0; jh < 2; ++jh) {
        __syncwarp();
#pragma unroll
        for (int i = 0; i < 2; ++i)
#pragma unroll
            for (int j = 0; j < 2; ++j)
                wmma::store_matrix_sync(stage + (i * 16) * 36 + j * 16,
                                        cf[i][jh * 2 + j], 36, wmma::mem_row_major);
        __syncwarp();
#pragma unroll
        for (int it = 0; it < 32; ++it) {
            float v = stage[it * 36 + lane];
            int grow = bm * 128 + wm * 32 + it;
            int gcol = bn * 128 + wn * 64 + jh * 32 + lane;
            if (projmode) {
                v += g_b_proj[gcol];
                if (gcol < 256) {
                    int b = grow / LQQ;
                    int rem = grow - b * LQQ;
                    int l = rem >> 10, yx = rem & 1023;
                    int h = gcol >> 5, d = gcol & 31;
                    g_vperm[((((b * NHH + h) * NLL + l) << 10) + yx) * HDD + d] =
                        __float2bfloat16(v);
                } else if (gcol < 1536) {
                    g_off[(size_t)grow * 1280 + (gcol - 256)] = v;
                } else {
                    g_aw[(size_t)grow * 640 + (gcol - 1536)] = v;
                }
            } else {
                v += bias[gcol];
                if (act) v = 0.5f * v * (1.0f + erff(v * 0.70710678118654752f));
                if (resid) v += resid[(size_t)grow * N + gcol];
                if (out_f32) out_f32[(size_t)grow * N + gcol] = v;
                if (out_bf16) out_bf16[(size_t)grow * N + gcol] = __float2bfloat16(v);
            }
        }
    }
}

// =====================================================================
// deformable sampling v4: two-phase + packed f32x2 accumulation
// =====================================================================
#define FFMA2(acc, v, w) \
    asm("fma.rn.f32x2 %0, %1, %2, %0;" : "+l"(acc) : "l"(v), "l"(w))

__global__ void sample_kernel(const float* __restrict__ refpts) {
    int warp = threadIdx.x >> 5, lane = threadIdx.x & 31;
    int unit = blockIdx.x * 8 + warp;                // 81920 units
    int token = unit >> 3;
    int h = unit & 7;
    int b = token / LQQ;

    __shared__ float s_aw[8][80];
    __shared__ float s_ref[8][10];
    __shared__ __align__(16) float s_wo[8][80 * 8];  // per sample: 4 x (wgt, byteoff)

    const float* awp = g_aw + (size_t)token * 640 + h * 80;
    for (int i = lane; i < 80; i += 32) s_aw[warp][i] = awp[i];
    const float* rp = refpts + (size_t)token * 10;
    if (lane < 10) s_ref[warp][lane] = rp[lane];
    __syncwarp();

    // ---- softmax over the 80 logits ----
    {
        float v0 = s_aw[warp][lane];
        float v1 = s_aw[warp][lane + 32];
        float v2 = (lane < 16) ? s_aw[warp][lane + 64] : -1e30f;
        float m = fmaxf(fmaxf(v0, v1), v2);
#pragma unroll
        for (int o = 16; o > 0; o >>= 1) m = fmaxf(m, __shfl_xor_sync(0xffffffffu, m, o));
        float e0 = expf(v0 - m), e1 = expf(v1 - m);
        float e2 = (lane < 16) ? expf(v2 - m) : 0.0f;
        float s = e0 + e1 + e2;
#pragma unroll
        for (int o = 16; o > 0; o >>= 1) s += __shfl_xor_sync(0xffffffffu, s, o);
        float inv = 1.0f / s;
        s_aw[warp][lane] = e0 * inv;
        s_aw[warp][lane + 32] = e1 * inv;
        if (lane < 16) s_aw[warp][lane + 64] = e2 * inv;
        __syncwarp();
    }

    // ---- phase 1: per-sample tap weights + BYTE offsets ----
    const float2* offp = (const float2*)(g_off + (size_t)token * 1280 + h * 160);
#pragma unroll
    for (int si = lane; si < 80; si += 32) {
        int l = si >> 4;
        float2 of = offp[si];
        float px = s_ref[warp][l * 2 + 0] * 32.0f - 0.5f + of.x;
        float py = s_ref[warp][l * 2 + 1] * 32.0f - 0.5f + of.y;
        float a  = s_aw[warp][si];
        float fx0 = floorf(px), fy0 = floorf(py);
        float fx = px - fx0, fy = py - fy0;
        int x0 = (int)fx0, y0 = (int)fy0;
        int lbase = l << 16;                       // level plane in BYTES
        float4 pk0, pk1;
        {   // tap 0
            bool ok = (x0 >= 0) && (x0 < 32) && (y0 >= 0) && (y0 < 32);
            int xc = min(max(x0, 0), 31), yc = min(max(y0, 0), 31);
            pk0.x = ok ? a * (1.0f - fx) * (1.0f - fy) : 0.0f;
            pk0.y = __int_as_float(lbase + (((yc << 5) + xc) << 6));
        }
        {   // tap 1
            int xi = x0 + 1;
            bool ok = (xi >= 0) && (xi < 32) && (y0 >= 0) && (y0 < 32);
            int xc = min(max(xi, 0), 31), yc = min(max(y0, 0), 31);
            pk0.z = ok ? a * fx * (1.0f - fy) : 0.0f;
            pk0.w = __int_as_float(lbase + (((yc << 5) + xc) << 6));
        }
        {   // tap 2
            int yi = y0 + 1;
            bool ok = (x0 >= 0) && (x0 < 32) && (yi >= 0) && (yi < 32);
            int xc = min(max(x0, 0), 31), yc = min(max(yi, 0), 31);
            pk1.x = ok ? a * (1.0f - fx) * fy : 0.0f;
            pk1.y = __int_as_float(lbase + (((yc << 5) + xc) << 6));
        }
        {   // tap 3
            int xi = x0 + 1, yi = y0 + 1;
            bool ok = (xi >= 0) && (xi < 32) && (yi >= 0) && (yi < 32);
            int xc = min(max(xi, 0), 31), yc = min(max(yi, 0), 31);
            pk1.z = ok ? a * fx * fy : 0.0f;
            pk1.w = __int_as_float(lbase + (((yc << 5) + xc) << 6));
        }
        *(float4*)&s_wo[warp][si * 8]     = pk0;
        *(float4*)&s_wo[warp][si * 8 + 4] = pk1;
    }
    __syncwarp();

    // ---- phase 2: load + packed f32x2 accumulate ----
    int q    = lane & 3;
    int tap  = (lane >> 2) & 3;
    int sgrp = lane >> 4;
    const float* wo = &s_wo[warp][tap * 2];
    const char* vbase = (const char*)
        (g_vperm + ((size_t)((b * NHH + h) * NLL) << 15) + (q << 3));

    uint64_t a0 = 0, a1 = 0, a2 = 0, a3 = 0;

#pragma unroll 8
    for (int r = 0; r < 40; ++r) {
        int s = r * 2 + sgrp;
        float2 p = *(const float2*)(wo + s * 8);
        uint32_t wb = __float_as_uint(p.x);
        uint64_t wpk;
        asm("mov.b64 %0, {%1, %2};" : "=l"(wpk) : "r"(wb), "r"(wb));
        uint4 u = *(const uint4*)(vbase + __float_as_int(p.y));
        uint64_t v;
        uint32_t lo, hi;
        lo = u.x << 16; hi = u.x & 0xFFFF0000u;
        asm("mov.b64 %0, {%1, %2};" : "=l"(v) : "r"(lo), "r"(hi));
        FFMA2(a0, v, wpk);
        lo = u.y << 16; hi = u.y & 0xFFFF0000u;
        asm("mov.b64 %0, {%1, %2};" : "=l"(v) : "r"(lo), "r"(hi));
        FFMA2(a1, v, wpk);
        lo = u.z << 16; hi = u.z & 0xFFFF0000u;
        asm("mov.b64 %0, {%1, %2};" : "=l"(v) : "r"(lo), "r"(hi));
        FFMA2(a2, v, wpk);
        lo = u.w << 16; hi = u.w & 0xFFFF0000u;
        asm("mov.b64 %0, {%1, %2};" : "=l"(v) : "r"(lo), "r"(hi));
        FFMA2(a3, v, wpk);
    }

    // unpack accumulators
    float2 acc0, acc1, acc2, acc3;
    {
        uint32_t lo, hi;
        asm("mov.b64 {%0, %1}, %2;" : "=r"(lo), "=r"(hi) : "l"(a0));
        acc0.x = __uint_as_float(lo); acc0.y = __uint_as_float(hi);
        asm("mov.b64 {%0, %1}, %2;" : "=r"(lo), "=r"(hi) : "l"(a1));
        acc1.x = __uint_as_float(lo); acc1.y = __uint_as_float(hi);
        asm("mov.b64 {%0, %1}, %2;" : "=r"(lo), "=r"(hi) : "l"(a2));
        acc2.x = __uint_as_float(lo); acc2.y = __uint_as_float(hi);
        asm("mov.b64 {%0, %1}, %2;" : "=r"(lo), "=r"(hi) : "l"(a3));
        acc3.x = __uint_as_float(lo); acc3.y = __uint_as_float(hi);
    }

    // reduce over tap (bits 2-3) and sgrp (bit 4)
#pragma unroll
    for (int o = 4; o <= 16; o <<= 1) {
        acc0.x += __shfl_xor_sync(0xffffffffu, acc0.x, o);
        acc0.y += __shfl_xor_sync(0xffffffffu, acc0.y, o);
        acc1.x += __shfl_xor_sync(0xffffffffu, acc1.x, o);
        acc1.y += __shfl_xor_sync(0xffffffffu, acc1.y, o);
        acc2.x += __shfl_xor_sync(0xffffffffu, acc2.x, o);
        acc2.y += __shfl_xor_sync(0xffffffffu, acc2.y, o);
        acc3.x += __shfl_xor_sync(0xffffffffu, acc3.x, o);
        acc3.y += __shfl_xor_sync(0xffffffffu, acc3.y, o);
    }

    if (lane < 4) {
        __nv_bfloat162 r0 = __floats2bfloat162_rn(acc0.x, acc0.y);
        __nv_bfloat162 r1 = __floats2bfloat162_rn(acc1.x, acc1.y);
        __nv_bfloat162 r2 = __floats2bfloat162_rn(acc2.x, acc2.y);
        __nv_bfloat162 r3 = __floats2bfloat162_rn(acc3.x, acc3.y);
        uint4 o;
        o.x = *(unsigned int*)&r0; o.y = *(unsigned int*)&r1;
        o.z = *(unsigned int*)&r2; o.w = *(unsigned int*)&r3;
        ((uint4*)(g_samp + (size_t)token * CC + h * 32))[q] = o;
    }
}

// =====================================================================
// launch  (order: pack_other, pack_proj, ln, gemm_proj <- ncu slot 4)
// =====================================================================
extern "C" void kernel_launch(void* const* d_in, const int* in_sizes, int n_in,
                              void* d_out, int out_size) {
    const float* x      = (const float*)d_in[0];
    const float* refpts = (const float*)d_in[1];
    const float* n3g = (const float*)d_in[4];
    const float* n3b = (const float*)d_in[5];
    const float* n4g = (const float*)d_in[6];
    const float* n4b = (const float*)d_in[7];
    const float* w_off  = (const float*)d_in[8];
    const float* b_off  = (const float*)d_in[9];
    const float* w_attn = (const float*)d_in[10];
    const float* b_attn = (const float*)d_in[11];
    const float* w_val  = (const float*)d_in[12];
    const float* b_val  = (const float*)d_in[13];
    const float* w_out  = (const float*)d_in[14];
    const float* b_out  = (const float*)d_in[15];
    const float* w_fc1  = (const float*)d_in[16];
    const float* b_fc1  = (const float*)d_in[17];
    const float* w_fc2  = (const float*)d_in[18];
    const float* b_fc2  = (const float*)d_in[19];
    float* outp = (float*)d_out;

    void *p_q, *p_hln, *p_samp, *p_mh, *p_x1;
    void *p_wp, *p_wou, *p_wf1, *p_wf2;
    cudaGetSymbolAddress(&p_q, g_q);
    cudaGetSymbolAddress(&p_hln, g_hln);
    cudaGetSymbolAddress(&p_samp, g_samp);
    cudaGetSymbolAddress(&p_mh, g_mh);
    cudaGetSymbolAddress(&p_x1, g_x1);
    cudaGetSymbolAddress(&p_wp, g_w_proj);
    cudaGetSymbolAddress(&p_wou, g_w_out);
    cudaGetSymbolAddress(&p_wf1, g_w_fc1);
    cudaGetSymbolAddress(&p_wf2, g_w_fc2);

    // 1-2. pack weights
    pack_other_kernel<<<(PACK_OTHER_TOTAL + 255) / 256, 256>>>(w_out, w_fc1, w_fc2);
    pack_proj_kernel<<<(PACK_PROJ_TOTAL + 255) / 256, 256>>>(
        w_val, w_off, w_attn, b_val, b_off, b_attn);

    // 3. q = LN(x)  (bf16)
    ln_kernel<<<MM / 8, 256>>>(x, n3g, n3b, (__nv_bfloat16*)p_q);

    // 4. fused projection GEMM (val->vperm, off, attn) N=2176  [ncu slot]
    gemm_bf16_kernel<<<dim3(NPROJ / 128, MM / 128), 256>>>(
        (const __nv_bfloat16*)p_q, (const __nv_bfloat16*)p_wp, nullptr,
        nullptr, nullptr, nullptr, MM, NPROJ, CC, 0, 1);

    // 5. deformable sampling v4 (+fused softmax) -> g_samp
    sample_kernel<<<MM * NHH / 8, 256>>>(refpts);

    // 6. out-proj + residual(x) -> x1 (f32)
    gemm_bf16_kernel<<<dim3(CC / 128, MM / 128), 256>>>(
        (const __nv_bfloat16*)p_samp, (const __nv_bfloat16*)p_wou, b_out,
        x, (float*)p_x1, nullptr, MM, CC, CC, 0, 0);

    // 7. h = LN(x1) (bf16)
    ln_kernel<<<MM / 8, 256>>>((const float*)p_x1, n4g, n4b, (__nv_bfloat16*)p_hln);

    // 8. fc1 + GELU -> mh (bf16)
    gemm_bf16_kernel<<<dim3(MLPH / 128, MM / 128), 256>>>(
        (const __nv_bfloat16*)p_hln, (const __nv_bfloat16*)p_wf1, b_fc1,
        nullptr, nullptr, (__nv_bfloat16*)p_mh, MM, MLPH, CC, 1, 0);

    // 9. fc2 + residual(x1) -> d_out (f32)
    gemm_bf16_kernel<<<dim3(CC / 128, MM / 128), 256>>>(
        (const __nv_bfloat16*)p_mh, (const __nv_bfloat16*)p_wf2, b_fc2,
        (const float*)p_x1, outp, nullptr, MM, CC, MLPH, 0, 0);
}

// round 9
// speedup vs baseline: 2.3338x; 1.0592x over previous
#include <cuda_runtime.h>
#include <cuda_bf16.h>
#include <mma.h>
#include <cstdint>

using namespace nvcuda;

// ---- problem constants ----
#define BD   2
#define CC   256
#define NHH  8
#define NLL  5
#define NPP  16
#define HDD  32
#define MLPH 1024
#define HWW  1024
#define LQQ  5120
#define MM   10240     // B * LQ tokens
#define NPROJ 2176     // 256 + 1280 + 640

// ---- scratch (device globals; no runtime allocation allowed) ----
__device__ __align__(256) __nv_bfloat16 g_q[MM * CC];
__device__ __align__(256) __nv_bfloat16 g_hln[MM * CC];
__device__ __align__(256) __nv_bfloat16 g_samp[MM * CC];
__device__ __align__(256) __nv_bfloat16 g_mh[MM * MLPH];
__device__ __align__(256) __nv_bfloat16 g_vperm[BD * NHH * NLL * HWW * HDD];
__device__ __align__(256) float g_off[MM * 1280];
__device__ __align__(256) float g_aw[MM * 640];
__device__ __align__(256) float g_x1[MM * CC];
__device__ __align__(256) __nv_bfloat16 g_w_proj[CC * NPROJ];
__device__ __align__(256) float g_b_proj[NPROJ];
__device__ __align__(256) __nv_bfloat16 g_w_out[CC * CC];
__device__ __align__(256) __nv_bfloat16 g_w_fc1[CC * MLPH];
__device__ __align__(256) __nv_bfloat16 g_w_fc2[MLPH * CC];

// cp.async helpers
#define CP16(dst, src) \
    asm volatile("cp.async.cg.shared.global [%0], [%1], 16;" :: "r"(dst), "l"(src))
#define CP_COMMIT() asm volatile("cp.async.commit_group;" ::: "memory")
#define CP_WAIT1()  asm volatile("cp.async.wait_group 1;" ::: "memory")
#define CP_WAIT0()  asm volatile("cp.async.wait_group 0;" ::: "memory")

// =====================================================================
// pack weights (two kernels so ncu slot 4 = proj GEMM)
// =====================================================================
#define PACK_PROJ_TOTAL (CC * NPROJ + NPROJ)

__global__ void pack_proj_kernel(const float* __restrict__ wv,
                                 const float* __restrict__ wo,
                                 const float* __restrict__ wa,
                                 const float* __restrict__ bv,
                                 const float* __restrict__ bo,
                                 const float* __restrict__ ba) {
    int i = blockIdx.x * 256 + threadIdx.x;
    if (i >= PACK_PROJ_TOTAL) return;
    if (i < CC * NPROJ) {
        int k = i / NPROJ, j = i - k * NPROJ;
        float v;
        if (j < 256)        v = wv[k * 256 + j];
        else if (j < 1536)  v = wo[k * 1280 + (j - 256)];
        else                v = wa[k * 640 + (j - 1536)];
        g_w_proj[i] = __float2bfloat16(v);
        return;
    }
    i -= CC * NPROJ;
    float v;
    if (i < 256)        v = bv[i];
    else if (i < 1536)  v = bo[i - 256];
    else                v = ba[i - 1536];
    g_b_proj[i] = v;
}

#define PACK_OTHER_TOTAL (CC*CC + CC*MLPH + MLPH*CC)
__global__ void pack_other_kernel(const float* __restrict__ wout,
                                  const float* __restrict__ wf1,
                                  const float* __restrict__ wf2) {
    int i = blockIdx.x * 256 + threadIdx.x;
    if (i < CC * CC) { g_w_out[i] = __float2bfloat16(wout[i]); return; }
    i -= CC * CC;
    if (i < CC * MLPH) { g_w_fc1[i] = __float2bfloat16(wf1[i]); return; }
    i -= CC * MLPH;
    if (i < MLPH * CC) g_w_fc2[i] = __float2bfloat16(wf2[i]);
}

// =====================================================================
// LayerNorm over C=256, one warp per row, bf16 output
// =====================================================================
__global__ void ln_kernel(const float* __restrict__ x,
                          const float* __restrict__ gam,
                          const float* __restrict__ bet,
                          __nv_bfloat16* __restrict__ out) {
    int warp = threadIdx.x >> 5, lane = threadIdx.x & 31;
    int row = blockIdx.x * 8 + warp;
    const float4* xp = (const float4*)(x + (size_t)row * CC);
    float4 a = xp[lane * 2];
    float4 b = xp[lane * 2 + 1];
    float s  = a.x + a.y + a.z + a.w + b.x + b.y + b.z + b.w;
    float sq = a.x*a.x + a.y*a.y + a.z*a.z + a.w*a.w
             + b.x*b.x + b.y*b.y + b.z*b.z + b.w*b.w;
#pragma unroll
    for (int o = 16; o > 0; o >>= 1) {
        s  += __shfl_xor_sync(0xffffffffu, s,  o);
        sq += __shfl_xor_sync(0xffffffffu, sq, o);
    }
    float mean = s * (1.0f / CC);
    float var  = sq * (1.0f / CC) - mean * mean;
    float rs   = rsqrtf(var + 1e-5f);
    const float4* gp = (const float4*)gam;
    const float4* bp = (const float4*)bet;
    float4 g0 = gp[lane * 2], g1 = gp[lane * 2 + 1];
    float4 b0 = bp[lane * 2], b1 = bp[lane * 2 + 1];
    float o0 = (a.x - mean) * rs * g0.x + b0.x;
    float o1 = (a.y - mean) * rs * g0.y + b0.y;
    float o2 = (a.z - mean) * rs * g0.z + b0.z;
    float o3 = (a.w - mean) * rs * g0.w + b0.w;
    float o4 = (b.x - mean) * rs * g1.x + b1.x;
    float o5 = (b.y - mean) * rs * g1.y + b1.y;
    float o6 = (b.z - mean) * rs * g1.z + b1.z;
    float o7 = (b.w - mean) * rs * g1.w + b1.w;
    __nv_bfloat162 r0 = __floats2bfloat162_rn(o0, o1);
    __nv_bfloat162 r1 = __floats2bfloat162_rn(o2, o3);
    __nv_bfloat162 r2 = __floats2bfloat162_rn(o4, o5);
    __nv_bfloat162 r3 = __floats2bfloat162_rn(o6, o7);
    uint4 u;
    u.x = *(unsigned int*)&r0; u.y = *(unsigned int*)&r1;
    u.z = *(unsigned int*)&r2; u.w = *(unsigned int*)&r3;
    ((uint4*)(out + (size_t)row * CC))[lane] = u;
}

// =====================================================================
// bf16 WMMA GEMM v3: block 128x128, 8 warps (4x2) of 32x64, K-step 32,
// 2-stage cp.async double buffering (overlap gmem load with MMA).
// Per-warp staged epilogue, stage stride 36 floats (16B multiple).
// projmode=1: fused projection epilogue (val->vperm bf16, off/attn->f32)
// =====================================================================
__global__ void gemm_bf16_kernel(const __nv_bfloat16* __restrict__ A,
                                 const __nv_bfloat16* __restrict__ Bw,
                                 const float* __restrict__ bias,
                                 const float* __restrict__ resid,
                                 float* __restrict__ out_f32,
                                 __nv_bfloat16* __restrict__ out_bf16,
                                 int M, int N, int K, int act, int projmode) {
    __shared__ __align__(16) unsigned char smem_raw[37888];
    // stage s: A at s*18944 (128 x 40 bf16), B at s*18944 + 10240 (32 x 136)

    int bm = blockIdx.y, bn = blockIdx.x;
    int tid = threadIdx.x;
    int w  = tid >> 5, lane = tid & 31;
    int wm = w >> 1, wn = w & 1;          // 4x2 warps, each 32(M) x 64(N)

    wmma::fragment<wmma::accumulator, 16, 16, 16, float> cf[2][4];
#pragma unroll
    for (int i = 0; i < 2; ++i)
#pragma unroll
        for (int j = 0; j < 4; ++j)
            wmma::fill_fragment(cf[i][j], 0.0f);

    const int steps = K >> 5;

    auto issue = [&](int buf, int k0) {
        __nv_bfloat16* sa = (__nv_bfloat16*)(smem_raw + buf * 18944);
        __nv_bfloat16* sb = (__nv_bfloat16*)(smem_raw + buf * 18944 + 10240);
#pragma unroll
        for (int u0 = 0; u0 < 2; ++u0) {        // A: 512 x 16B
            int c = tid + u0 * 256;
            int row = c >> 2, c8 = (c & 3) << 3;
            unsigned dst = (unsigned)__cvta_generic_to_shared(sa + row * 40 + c8);
            CP16(dst, A + (size_t)(bm * 128 + row) * K + k0 + c8);
        }
#pragma unroll
        for (int u0 = 0; u0 < 2; ++u0) {        // B: 512 x 16B
            int c = tid + u0 * 256;
            int row = c >> 4, c8 = (c & 15) << 3;
            unsigned dst = (unsigned)__cvta_generic_to_shared(sb + row * 136 + c8);
            CP16(dst, Bw + (size_t)(k0 + row) * N + bn * 128 + c8);
        }
    };

    issue(0, 0); CP_COMMIT();

    for (int s = 0; s < steps; ++s) {
        int cur = s & 1;
        if (s + 1 < steps) { issue((s + 1) & 1, (s + 1) << 5); CP_COMMIT(); CP_WAIT1(); }
        else               { CP_WAIT0(); }
        __syncthreads();

        __nv_bfloat16* sa = (__nv_bfloat16*)(smem_raw + cur * 18944);
        __nv_bfloat16* sb = (__nv_bfloat16*)(smem_raw + cur * 18944 + 10240);
#pragma unroll
        for (int kk = 0; kk < 32; kk += 16) {
            wmma::fragment<wmma::matrix_a, 16, 16, 16, __nv_bfloat16, wmma::row_major> af[2];
            wmma::fragment<wmma::matrix_b, 16, 16, 16, __nv_bfloat16, wmma::row_major> bf[4];
#pragma unroll
            for (int i = 0; i < 2; ++i)
                wmma::load_matrix_sync(af[i], sa + (wm * 32 + i * 16) * 40 + kk, 40);
#pragma unroll
            for (int j = 0; j < 4; ++j)
                wmma::load_matrix_sync(bf[j], sb + kk * 136 + wn * 64 + j * 16, 136);
#pragma unroll
            for (int i = 0; i < 2; ++i)
#pragma unroll
                for (int j = 0; j < 4; ++j)
                    wmma::mma_sync(cf[i][j], af[i], bf[j], cf[i][j]);
        }
        __syncthreads();
    }

    // per-warp staged epilogue: two 32x32 passes, stage stride 36 (16B mult)
    float* stage = (float*)smem_raw + w * 1152;   // 32*36 floats = 4608B/warp
#pragma unroll
    for (int jh = 0; jh < 2; ++jh) {
        __syncwarp();
#pragma unroll
        for (int i = 0; i < 2; ++i)
#pragma unroll
            for (int j = 0; j < 2; ++j)
                wmma::store_matrix_sync(stage + (i * 16) * 36 + j * 16,
                                        cf[i][jh * 2 + j], 36, wmma::mem_row_major);
        __syncwarp();
#pragma unroll
        for (int it = 0; it < 32; ++it) {
            float v = stage[it * 36 + lane];
            int grow = bm * 128 + wm * 32 + it;
            int gcol = bn * 128 + wn * 64 + jh * 32 + lane;
            if (projmode) {
                v += g_b_proj[gcol];
                if (gcol < 256) {
                    int b = grow / LQQ;
                    int rem = grow - b * LQQ;
                    int l = rem >> 10, yx = rem & 1023;
                    int h = gcol >> 5, d = gcol & 31;
                    g_vperm[((((b * NHH + h) * NLL + l) << 10) + yx) * HDD + d] =
                        __float2bfloat16(v);
                } else if (gcol < 1536) {
                    g_off[(size_t)grow * 1280 + (gcol - 256)] = v;
                } else {
                    g_aw[(size_t)grow * 640 + (gcol - 1536)] = v;
                }
            } else {
                v += bias[gcol];
                if (act) v = 0.5f * v * (1.0f + erff(v * 0.70710678118654752f));
                if (resid) v += resid[(size_t)grow * N + gcol];
                if (out_f32) out_f32[(size_t)grow * N + gcol] = v;
                if (out_bf16) out_bf16[(size_t)grow * N + gcol] = __float2bfloat16(v);
            }
        }
    }
}

// =====================================================================
// deformable sampling v4: two-phase + packed f32x2 accumulation
// =====================================================================
#define FFMA2(acc, v, w) \
    asm("fma.rn.f32x2 %0, %1, %2, %0;" : "+l"(acc) : "l"(v), "l"(w))

__global__ void sample_kernel(const float* __restrict__ refpts) {
    int warp = threadIdx.x >> 5, lane = threadIdx.x & 31;
    int unit = blockIdx.x * 8 + warp;                // 81920 units
    int token = unit >> 3;
    int h = unit & 7;
    int b = token / LQQ;

    __shared__ float s_aw[8][80];
    __shared__ float s_ref[8][10];
    __shared__ __align__(16) float s_wo[8][80 * 8];  // per sample: 4 x (wgt, byteoff)

    const float* awp = g_aw + (size_t)token * 640 + h * 80;
    for (int i = lane; i < 80; i += 32) s_aw[warp][i] = awp[i];
    const float* rp = refpts + (size_t)token * 10;
    if (lane < 10) s_ref[warp][lane] = rp[lane];
    __syncwarp();

    // ---- softmax over the 80 logits ----
    {
        float v0 = s_aw[warp][lane];
        float v1 = s_aw[warp][lane + 32];
        float v2 = (lane < 16) ? s_aw[warp][lane + 64] : -1e30f;
        float m = fmaxf(fmaxf(v0, v1), v2);
#pragma unroll
        for (int o = 16; o > 0; o >>= 1) m = fmaxf(m, __shfl_xor_sync(0xffffffffu, m, o));
        float e0 = expf(v0 - m), e1 = expf(v1 - m);
        float e2 = (lane < 16) ? expf(v2 - m) : 0.0f;
        float s = e0 + e1 + e2;
#pragma unroll
        for (int o = 16; o > 0; o >>= 1) s += __shfl_xor_sync(0xffffffffu, s, o);
        float inv = 1.0f / s;
        s_aw[warp][lane] = e0 * inv;
        s_aw[warp][lane + 32] = e1 * inv;
        if (lane < 16) s_aw[warp][lane + 64] = e2 * inv;
        __syncwarp();
    }

    // ---- phase 1: per-sample tap weights + BYTE offsets ----
    const float2* offp = (const float2*)(g_off + (size_t)token * 1280 + h * 160);
#pragma unroll
    for (int si = lane; si < 80; si += 32) {
        int l = si >> 4;
        float2 of = offp[si];
        float px = s_ref[warp][l * 2 + 0] * 32.0f - 0.5f + of.x;
        float py = s_ref[warp][l * 2 + 1] * 32.0f - 0.5f + of.y;
        float a  = s_aw[warp][si];
        float fx0 = floorf(px), fy0 = floorf(py);
        float fx = px - fx0, fy = py - fy0;
        int x0 = (int)fx0, y0 = (int)fy0;
        int lbase = l << 16;                       // level plane in BYTES
        float4 pk0, pk1;
        {   // tap 0
            bool ok = (x0 >= 0) && (x0 < 32) && (y0 >= 0) && (y0 < 32);
            int xc = min(max(x0, 0), 31), yc = min(max(y0, 0), 31);
            pk0.x = ok ? a * (1.0f - fx) * (1.0f - fy) : 0.0f;
            pk0.y = __int_as_float(lbase + (((yc << 5) + xc) << 6));
        }
        {   // tap 1
            int xi = x0 + 1;
            bool ok = (xi >= 0) && (xi < 32) && (y0 >= 0) && (y0 < 32);
            int xc = min(max(xi, 0), 31), yc = min(max(y0, 0), 31);
            pk0.z = ok ? a * fx * (1.0f - fy) : 0.0f;
            pk0.w = __int_as_float(lbase + (((yc << 5) + xc) << 6));
        }
        {   // tap 2
            int yi = y0 + 1;
            bool ok = (x0 >= 0) && (x0 < 32) && (yi >= 0) && (yi < 32);
            int xc = min(max(x0, 0), 31), yc = min(max(yi, 0), 31);
            pk1.x = ok ? a * (1.0f - fx) * fy : 0.0f;
            pk1.y = __int_as_float(lbase + (((yc << 5) + xc) << 6));
        }
        {   // tap 3
            int xi = x0 + 1, yi = y0 + 1;
            bool ok = (xi >= 0) && (xi < 32) && (yi >= 0) && (yi < 32);
            int xc = min(max(xi, 0), 31), yc = min(max(yi, 0), 31);
            pk1.z = ok ? a * fx * fy : 0.0f;
            pk1.w = __int_as_float(lbase + (((yc << 5) + xc) << 6));
        }
        *(float4*)&s_wo[warp][si * 8]     = pk0;
        *(float4*)&s_wo[warp][si * 8 + 4] = pk1;
    }
    __syncwarp();

    // ---- phase 2: load + packed f32x2 accumulate ----
    int q    = lane & 3;
    int tap  = (lane >> 2) & 3;
    int sgrp = lane >> 4;
    const float* wo = &s_wo[warp][tap * 2];
    const char* vbase = (const char*)
        (g_vperm + ((size_t)((b * NHH + h) * NLL) << 15) + (q << 3));

    uint64_t a0 = 0, a1 = 0, a2 = 0, a3 = 0;

#pragma unroll 8
    for (int r = 0; r < 40; ++r) {
        int s = r * 2 + sgrp;
        float2 p = *(const float2*)(wo + s * 8);
        uint32_t wb = __float_as_uint(p.x);
        uint64_t wpk;
        asm("mov.b64 %0, {%1, %2};" : "=l"(wpk) : "r"(wb), "r"(wb));
        uint4 u = *(const uint4*)(vbase + __float_as_int(p.y));
        uint64_t v;
        uint32_t lo, hi;
        lo = u.x << 16; hi = u.x & 0xFFFF0000u;
        asm("mov.b64 %0, {%1, %2};" : "=l"(v) : "r"(lo), "r"(hi));
        FFMA2(a0, v, wpk);
        lo = u.y << 16; hi = u.y & 0xFFFF0000u;
        asm("mov.b64 %0, {%1, %2};" : "=l"(v) : "r"(lo), "r"(hi));
        FFMA2(a1, v, wpk);
        lo = u.z << 16; hi = u.z & 0xFFFF0000u;
        asm("mov.b64 %0, {%1, %2};" : "=l"(v) : "r"(lo), "r"(hi));
        FFMA2(a2, v, wpk);
        lo = u.w << 16; hi = u.w & 0xFFFF0000u;
        asm("mov.b64 %0, {%1, %2};" : "=l"(v) : "r"(lo), "r"(hi));
        FFMA2(a3, v, wpk);
    }

    // unpack accumulators
    float2 acc0, acc1, acc2, acc3;
    {
        uint32_t lo, hi;
        asm("mov.b64 {%0, %1}, %2;" : "=r"(lo), "=r"(hi) : "l"(a0));
        acc0.x = __uint_as_float(lo); acc0.y = __uint_as_float(hi);
        asm("mov.b64 {%0, %1}, %2;" : "=r"(lo), "=r"(hi) : "l"(a1));
        acc1.x = __uint_as_float(lo); acc1.y = __uint_as_float(hi);
        asm("mov.b64 {%0, %1}, %2;" : "=r"(lo), "=r"(hi) : "l"(a2));
        acc2.x = __uint_as_float(lo); acc2.y = __uint_as_float(hi);
        asm("mov.b64 {%0, %1}, %2;" : "=r"(lo), "=r"(hi) : "l"(a3));
        acc3.x = __uint_as_float(lo); acc3.y = __uint_as_float(hi);
    }

    // reduce over tap (bits 2-3) and sgrp (bit 4)
#pragma unroll
    for (int o = 4; o <= 16; o <<= 1) {
        acc0.x += __shfl_xor_sync(0xffffffffu, acc0.x, o);
        acc0.y += __shfl_xor_sync(0xffffffffu, acc0.y, o);
        acc1.x += __shfl_xor_sync(0xffffffffu, acc1.x, o);
        acc1.y += __shfl_xor_sync(0xffffffffu, acc1.y, o);
        acc2.x += __shfl_xor_sync(0xffffffffu, acc2.x, o);
        acc2.y += __shfl_xor_sync(0xffffffffu, acc2.y, o);
        acc3.x += __shfl_xor_sync(0xffffffffu, acc3.x, o);
        acc3.y += __shfl_xor_sync(0xffffffffu, acc3.y, o);
    }

    if (lane < 4) {
        __nv_bfloat162 r0 = __floats2bfloat162_rn(acc0.x, acc0.y);
        __nv_bfloat162 r1 = __floats2bfloat162_rn(acc1.x, acc1.y);
        __nv_bfloat162 r2 = __floats2bfloat162_rn(acc2.x, acc2.y);
        __nv_bfloat162 r3 = __floats2bfloat162_rn(acc3.x, acc3.y);
        uint4 o;
        o.x = *(unsigned int*)&r0; o.y = *(unsigned int*)&r1;
        o.z = *(unsigned int*)&r2; o.w = *(unsigned int*)&r3;
        ((uint4*)(g_samp + (size_t)token * CC + h * 32))[q] = o;
    }
}

// =====================================================================
// launch  (order: pack_other, pack_proj, ln, gemm_proj <- ncu slot 4)
// =====================================================================
extern "C" void kernel_launch(void* const* d_in, const int* in_sizes, int n_in,
                              void* d_out, int out_size) {
    const float* x      = (const float*)d_in[0];
    const float* refpts = (const float*)d_in[1];
    const float* n3g = (const float*)d_in[4];
    const float* n3b = (const float*)d_in[5];
    const float* n4g = (const float*)d_in[6];
    const float* n4b = (const float*)d_in[7];
    const float* w_off  = (const float*)d_in[8];
    const float* b_off  = (const float*)d_in[9];
    const float* w_attn = (const float*)d_in[10];
    const float* b_attn = (const float*)d_in[11];
    const float* w_val  = (const float*)d_in[12];
    const float* b_val  = (const float*)d_in[13];
    const float* w_out  = (const float*)d_in[14];
    const float* b_out  = (const float*)d_in[15];
    const float* w_fc1  = (const float*)d_in[16];
    const float* b_fc1  = (const float*)d_in[17];
    const float* w_fc2  = (const float*)d_in[18];
    const float* b_fc2  = (const float*)d_in[19];
    float* outp = (float*)d_out;

    void *p_q, *p_hln, *p_samp, *p_mh, *p_x1;
    void *p_wp, *p_wou, *p_wf1, *p_wf2;
    cudaGetSymbolAddress(&p_q, g_q);
    cudaGetSymbolAddress(&p_hln, g_hln);
    cudaGetSymbolAddress(&p_samp, g_samp);
    cudaGetSymbolAddress(&p_mh, g_mh);
    cudaGetSymbolAddress(&p_x1, g_x1);
    cudaGetSymbolAddress(&p_wp, g_w_proj);
    cudaGetSymbolAddress(&p_wou, g_w_out);
    cudaGetSymbolAddress(&p_wf1, g_w_fc1);
    cudaGetSymbolAddress(&p_wf2, g_w_fc2);

    // 1-2. pack weights
    pack_other_kernel<<<(PACK_OTHER_TOTAL + 255) / 256, 256>>>(w_out, w_fc1, w_fc2);
    pack_proj_kernel<<<(PACK_PROJ_TOTAL + 255) / 256, 256>>>(
        w_val, w_off, w_attn, b_val, b_off, b_attn);

    // 3. q = LN(x)  (bf16)
    ln_kernel<<<MM / 8, 256>>>(x, n3g, n3b, (__nv_bfloat16*)p_q);

    // 4. fused projection GEMM (val->vperm, off, attn) N=2176  [ncu slot]
    gemm_bf16_kernel<<<dim3(NPROJ / 128, MM / 128), 256>>>(
        (const __nv_bfloat16*)p_q, (const __nv_bfloat16*)p_wp, nullptr,
        nullptr, nullptr, nullptr, MM, NPROJ, CC, 0, 1);

    // 5. deformable sampling v4 (+fused softmax) -> g_samp
    sample_kernel<<<MM * NHH / 8, 256>>>(refpts);

    // 6. out-proj + residual(x) -> x1 (f32)
    gemm_bf16_kernel<<<dim3(CC / 128, MM / 128), 256>>>(
        (const __nv_bfloat16*)p_samp, (const __nv_bfloat16*)p_wou, b_out,
        x, (float*)p_x1, nullptr, MM, CC, CC, 0, 0);

    // 7. h = LN(x1) (bf16)
    ln_kernel<<<MM / 8, 256>>>((const float*)p_x1, n4g, n4b, (__nv_bfloat16*)p_hln);

    // 8. fc1 + GELU -> mh (bf16)
    gemm_bf16_kernel<<<dim3(MLPH / 128, MM / 128), 256>>>(
        (const __nv_bfloat16*)p_hln, (const __nv_bfloat16*)p_wf1, b_fc1,
        nullptr, nullptr, (__nv_bfloat16*)p_mh, MM, MLPH, CC, 1, 0);

    // 9. fc2 + residual(x1) -> d_out (f32)
    gemm_bf16_kernel<<<dim3(CC / 128, MM / 128), 256>>>(
        (const __nv_bfloat16*)p_mh, (const __nv_bfloat16*)p_wf2, b_fc2,
        (const float*)p_x1, outp, nullptr, MM, CC, MLPH, 0, 0);
}